// round 2
// baseline (speedup 1.0000x reference)
#include <cuda_runtime.h>
#include <math.h>

#define T_ 512
#define B_ 64
#define I_ 1024
#define H_ 1024
#define O_ 1024
#define TB_ (T_ * B_)
#define NBLK 128

// ---------------- scratch (device globals; no allocations allowed) -------------
__device__ float g_xr[TB_ * H_];   // X @ W_xr + b_r
__device__ float g_xu[TB_ * H_];   // X @ W_xu + b_u
__device__ float g_xh[TB_ * H_];   // X @ W_xh + b_h
__device__ float g_h [B_ * H_];    // current hidden state
__device__ float g_hR[B_ * H_];    // h * R (input to candidate GEMM)
__device__ float g_U [B_ * H_];    // update gate
__device__ float g_WrT[H_ * H_];   // W_hr transposed: [n][k]
__device__ float g_WuT[H_ * H_];   // W_hu transposed
__device__ float g_WhT[H_ * H_];   // W_hh transposed
__device__ unsigned int g_bar_cnt; // grid barrier counter

// ---------------- init: zero h, reset barrier --------------------------------
__global__ void init_kernel() {
    int i = blockIdx.x * blockDim.x + threadIdx.x;
    if (i == 0) g_bar_cnt = 0;
    if (i < B_ * H_) g_h[i] = 0.0f;
}

// ---------------- 32x32 tiled transpose: out[n][k] = in[k][n] -----------------
__global__ __launch_bounds__(256) void transpose_kernel(
    const float* __restrict__ in, float* __restrict__ out)
{
    __shared__ float tile[32][33];
    int bx = blockIdx.x * 32;   // n base
    int by = blockIdx.y * 32;   // k base
    int tx = threadIdx.x;       // 0..31
    int ty = threadIdx.y;       // 0..7
#pragma unroll
    for (int j = 0; j < 32; j += 8)
        tile[ty + j][tx] = in[(size_t)(by + ty + j) * H_ + bx + tx];
    __syncthreads();
#pragma unroll
    for (int j = 0; j < 32; j += 8)
        out[(size_t)(bx + ty + j) * H_ + by + tx] = tile[tx][ty + j];
}

// ---------------- big SGEMM: C[M,N] = A[M,K] @ W[K,N] + bias[N] ---------------
__global__ __launch_bounds__(256) void sgemm_bias_kernel(
    const float* __restrict__ A, const float* __restrict__ W,
    const float* __restrict__ bias, float* __restrict__ C,
    int M, int N, int K)
{
    __shared__ float As[8][128];
    __shared__ float Bs[8][128];

    const int tid  = threadIdx.x;
    const int row0 = blockIdx.y * 128;
    const int col0 = blockIdx.x * 128;
    const int tx   = tid & 15;
    const int ty   = tid >> 4;

    const int arow = tid >> 1;
    const int ak   = (tid & 1) * 4;
    const int wrow = tid >> 5;
    const int wcol = (tid & 31) * 4;

    const float* Aptr = A + (size_t)(row0 + arow) * K + ak;
    const float* Wptr = W + (size_t)wrow * N + col0 + wcol;

    float acc[8][8];
#pragma unroll
    for (int i = 0; i < 8; i++)
#pragma unroll
        for (int j = 0; j < 8; j++) acc[i][j] = 0.0f;

    for (int k0 = 0; k0 < K; k0 += 8) {
        float4 av = *reinterpret_cast<const float4*>(Aptr + k0);
        float4 wv = *reinterpret_cast<const float4*>(Wptr + (size_t)k0 * N);
        __syncthreads();
        As[ak + 0][arow] = av.x;
        As[ak + 1][arow] = av.y;
        As[ak + 2][arow] = av.z;
        As[ak + 3][arow] = av.w;
        *reinterpret_cast<float4*>(&Bs[wrow][wcol]) = wv;
        __syncthreads();
#pragma unroll
        for (int kk = 0; kk < 8; kk++) {
            float4 a0 = *reinterpret_cast<const float4*>(&As[kk][ty * 8]);
            float4 a1 = *reinterpret_cast<const float4*>(&As[kk][ty * 8 + 4]);
            float4 b0 = *reinterpret_cast<const float4*>(&Bs[kk][tx * 8]);
            float4 b1 = *reinterpret_cast<const float4*>(&Bs[kk][tx * 8 + 4]);
            float a[8] = {a0.x, a0.y, a0.z, a0.w, a1.x, a1.y, a1.z, a1.w};
            float b[8] = {b0.x, b0.y, b0.z, b0.w, b1.x, b1.y, b1.z, b1.w};
#pragma unroll
            for (int i = 0; i < 8; i++)
#pragma unroll
                for (int j = 0; j < 8; j++) acc[i][j] += a[i] * b[j];
        }
    }

#pragma unroll
    for (int i = 0; i < 8; i++) {
        int r = row0 + ty * 8 + i;
        float* Crow = C + (size_t)r * N + col0 + tx * 8;
        const float* bp = bias + col0 + tx * 8;
#pragma unroll
        for (int j = 0; j < 8; j++) Crow[j] = acc[i][j] + bp[j];
    }
}

// ---------------- grid barrier ------------------------------------------------
__device__ __forceinline__ void grid_sync() {
    __syncthreads();
    if (threadIdx.x == 0) {
        __threadfence();
        unsigned int old = atomicAdd(&g_bar_cnt, 1);
        unsigned int target = (old / NBLK) * NBLK + NBLK;
        while (*(volatile unsigned int*)&g_bar_cnt < target) { }
        __threadfence();
    }
    __syncthreads();
}

// ---------------- persistent GRU recurrence -----------------------------------
// 128 blocks x 256 threads, 512 timesteps, 2 phases + 2 grid barriers per step.
// Phase A: blocks 0..63 compute R cols [bid*16,+16) -> g_hR = h*sigmoid(.)
//          blocks 64..127 compute U cols             -> g_U
// Phase B: block bid computes candidate cols [bid*8,+8), updates g_h, writes states.
__global__ __launch_bounds__(256) void gru_persistent_kernel(float* __restrict__ states)
{
    __shared__ float4 hs4[64][16];   // 64 rows x 64 k-values per chunk

    const int tid = threadIdx.x;
    const int bid = blockIdx.x;

    // phase A thread mapping
    const int a_gate = bid >> 6;                 // 0 = R, 1 = U
    const int a_n    = (bid & 63) * 16 + (tid & 15);
    const int a_r0   = (tid >> 4) * 4;           // 4 batch rows
    const float* a_WT = (a_gate ? g_WuT : g_WrT) + (size_t)a_n * H_;
    const float* a_x  = a_gate ? g_xu : g_xr;

    // phase B thread mapping
    const int b_n  = bid * 8 + (tid & 7);
    const int b_r0 = (tid >> 3) * 2;             // 2 batch rows
    const float* b_WT = g_WhT + (size_t)b_n * H_;

    // chunk-copy mapping
    const int c_r  = tid >> 2;                   // 0..63
    const int c_kb = tid & 3;                    // float4 slot base

    for (int t = 0; t < T_; t++) {
        // ===================== phase A: gates =====================
        {
            float acc0 = 0.f, acc1 = 0.f, acc2 = 0.f, acc3 = 0.f;
            const float4* WT4 = reinterpret_cast<const float4*>(a_WT);
            for (int k0 = 0; k0 < H_; k0 += 64) {
                __syncthreads();
                {
                    const float4* src = reinterpret_cast<const float4*>(g_h + c_r * H_ + k0);
#pragma unroll
                    for (int j = 0; j < 4; j++)
                        hs4[c_r][c_kb + j * 4] = __ldcg(&src[c_kb + j * 4]);
                }
                __syncthreads();
                const float4* w4 = WT4 + (k0 >> 2);
#pragma unroll
                for (int kq = 0; kq < 16; kq++) {
                    float4 w  = w4[kq];
                    float4 h0 = hs4[a_r0 + 0][kq];
                    float4 h1 = hs4[a_r0 + 1][kq];
                    float4 h2 = hs4[a_r0 + 2][kq];
                    float4 h3 = hs4[a_r0 + 3][kq];
                    acc0 += w.x * h0.x + w.y * h0.y + w.z * h0.z + w.w * h0.w;
                    acc1 += w.x * h1.x + w.y * h1.y + w.z * h1.z + w.w * h1.w;
                    acc2 += w.x * h2.x + w.y * h2.y + w.z * h2.z + w.w * h2.w;
                    acc3 += w.x * h3.x + w.y * h3.y + w.z * h3.z + w.w * h3.w;
                }
            }
            const size_t xbase = (size_t)t * B_ * H_;
            float accs[4] = {acc0, acc1, acc2, acc3};
#pragma unroll
            for (int i = 0; i < 4; i++) {
                int r = a_r0 + i;
                float pre = accs[i] + a_x[xbase + (size_t)r * H_ + a_n];
                float s = 1.0f / (1.0f + __expf(-pre));
                if (a_gate) g_U[r * H_ + a_n] = s;
                else        g_hR[r * H_ + a_n] = g_h[r * H_ + a_n] * s;
            }
        }
        grid_sync();

        // ===================== phase B: candidate + update =====================
        {
            float acc0 = 0.f, acc1 = 0.f;
            const float4* WT4 = reinterpret_cast<const float4*>(b_WT);
            for (int k0 = 0; k0 < H_; k0 += 64) {
                __syncthreads();
                {
                    const float4* src = reinterpret_cast<const float4*>(g_hR + c_r * H_ + k0);
#pragma unroll
                    for (int j = 0; j < 4; j++)
                        hs4[c_r][c_kb + j * 4] = __ldcg(&src[c_kb + j * 4]);
                }
                __syncthreads();
                const float4* w4 = WT4 + (k0 >> 2);
#pragma unroll
                for (int kq = 0; kq < 16; kq++) {
                    float4 w  = w4[kq];
                    float4 h0 = hs4[b_r0 + 0][kq];
                    float4 h1 = hs4[b_r0 + 1][kq];
                    acc0 += w.x * h0.x + w.y * h0.y + w.z * h0.z + w.w * h0.w;
                    acc1 += w.x * h1.x + w.y * h1.y + w.z * h1.z + w.w * h1.w;
                }
            }
            const size_t xbase = (size_t)t * B_ * H_;
            float accs[2] = {acc0, acc1};
#pragma unroll
            for (int i = 0; i < 2; i++) {
                int r = b_r0 + i;
                float hc   = tanhf(accs[i] + g_xh[xbase + (size_t)r * H_ + b_n]);
                float u    = g_U[r * H_ + b_n];
                float hold = g_h[r * H_ + b_n];
                float hnew = u * hold + (1.0f - u) * hc;
                g_h[r * H_ + b_n] = hnew;
                states[xbase + (size_t)r * H_ + b_n] = hnew;
            }
        }
        grid_sync();
    }
}

// ---------------- launcher ----------------------------------------------------
extern "C" void kernel_launch(void* const* d_in, const int* in_sizes, int n_in,
                              void* d_out, int out_size)
{
    const float* X    = (const float*)d_in[0];
    const float* W_xr = (const float*)d_in[1];
    const float* W_xu = (const float*)d_in[2];
    const float* W_xh = (const float*)d_in[3];
    const float* W_hr = (const float*)d_in[4];
    const float* W_hu = (const float*)d_in[5];
    const float* W_hh = (const float*)d_in[6];
    const float* b_r  = (const float*)d_in[7];
    const float* b_u  = (const float*)d_in[8];
    const float* b_h  = (const float*)d_in[9];
    const float* W_hq = (const float*)d_in[10];
    const float* b_q  = (const float*)d_in[11];

    float* out     = (float*)d_out;
    float* outputs = out;                        // [T,B,O]
    float* states  = out + (size_t)TB_ * O_;     // [T,B,H]

    void *p_xr, *p_xu, *p_xh, *p_wrt, *p_wut, *p_wht;
    cudaGetSymbolAddress(&p_xr, g_xr);
    cudaGetSymbolAddress(&p_xu, g_xu);
    cudaGetSymbolAddress(&p_xh, g_xh);
    cudaGetSymbolAddress(&p_wrt, g_WrT);
    cudaGetSymbolAddress(&p_wut, g_WuT);
    cudaGetSymbolAddress(&p_wht, g_WhT);

    // 1) reset hidden state + barrier counter
    init_kernel<<<(B_ * H_ + 255) / 256, 256>>>();

    // 2) transpose recurrent weights to [n][k]
    dim3 tb(32, 8), tg(H_ / 32, H_ / 32);
    transpose_kernel<<<tg, tb>>>(W_hr, (float*)p_wrt);
    transpose_kernel<<<tg, tb>>>(W_hu, (float*)p_wut);
    transpose_kernel<<<tg, tb>>>(W_hh, (float*)p_wht);

    // 3) input projections: [TB, I] @ [I, H] + b
    dim3 gproj(H_ / 128, TB_ / 128);
    sgemm_bias_kernel<<<gproj, 256>>>(X, W_xr, b_r, (float*)p_xr, TB_, H_, I_);
    sgemm_bias_kernel<<<gproj, 256>>>(X, W_xu, b_u, (float*)p_xu, TB_, H_, I_);
    sgemm_bias_kernel<<<gproj, 256>>>(X, W_xh, b_h, (float*)p_xh, TB_, H_, I_);

    // 4) recurrence: one persistent kernel, 512 steps internally
    gru_persistent_kernel<<<NBLK, 256>>>(states);

    // 5) output projection: states [TB, H] @ [H, O] + b_q
    dim3 gout(O_ / 128, TB_ / 128);
    sgemm_bias_kernel<<<gout, 256>>>(states, W_hq, b_q, outputs, TB_, O_, H_);
}

// round 3
// speedup vs baseline: 2.3615x; 2.3615x over previous
#include <cuda_runtime.h>
#include <math.h>

#define T_ 512
#define B_ 64
#define I_ 1024
#define H_ 1024
#define O_ 1024
#define TB_ (T_ * B_)
#define NBLK 128

// ---------------- scratch (device globals; no allocations allowed) -------------
__device__ float g_xr[TB_ * H_];   // X @ W_xr + b_r
__device__ float g_xu[TB_ * H_];   // X @ W_xu + b_u
__device__ float g_xh[TB_ * H_];   // X @ W_xh + b_h
__device__ float g_h [B_ * H_];    // current hidden state
__device__ float g_hR[B_ * H_];    // h * R
__device__ float g_U [B_ * H_];    // update gate
__device__ float g_WrP[H_ * H_];   // W_hr packed [colblk16][k][16]
__device__ float g_WuP[H_ * H_];   // W_hu packed [colblk16][k][16]
__device__ float g_WhP[H_ * H_];   // W_hh packed [colblk8][k][8]
__device__ unsigned int g_bar_cnt;

// ---------------- init --------------------------------------------------------
__global__ void init_kernel() {
    int i = blockIdx.x * blockDim.x + threadIdx.x;
    if (i == 0) g_bar_cnt = 0;
    if (i < B_ * H_) g_h[i] = 0.0f;
}

// ---------------- weight repack ------------------------------------------------
// P[(n/16)*H*16 + k*16 + (n%16)] = W[k*H + n]
__global__ __launch_bounds__(256) void pack16_kernel(
    const float* __restrict__ W, float* __restrict__ P)
{
    int idx = blockIdx.x * 256 + threadIdx.x;
    int k = idx >> 10, n = idx & (H_ - 1);
    P[(((size_t)(n >> 4) * H_ + k) << 4) + (n & 15)] = W[idx];
}
__global__ __launch_bounds__(256) void pack8_kernel(
    const float* __restrict__ W, float* __restrict__ P)
{
    int idx = blockIdx.x * 256 + threadIdx.x;
    int k = idx >> 10, n = idx & (H_ - 1);
    P[(((size_t)(n >> 3) * H_ + k) << 3) + (n & 7)] = W[idx];
}

// ---------------- big SGEMM: C[M,N] = A[M,K] @ W[K,N] + bias[N] ---------------
__global__ __launch_bounds__(256) void sgemm_bias_kernel(
    const float* __restrict__ A, const float* __restrict__ W,
    const float* __restrict__ bias, float* __restrict__ C,
    int M, int N, int K)
{
    __shared__ float As[8][128];
    __shared__ float Bs[8][128];

    const int tid  = threadIdx.x;
    const int row0 = blockIdx.y * 128;
    const int col0 = blockIdx.x * 128;
    const int tx   = tid & 15;
    const int ty   = tid >> 4;

    const int arow = tid >> 1;
    const int ak   = (tid & 1) * 4;
    const int wrow = tid >> 5;
    const int wcol = (tid & 31) * 4;

    const float* Aptr = A + (size_t)(row0 + arow) * K + ak;
    const float* Wptr = W + (size_t)wrow * N + col0 + wcol;

    float acc[8][8];
#pragma unroll
    for (int i = 0; i < 8; i++)
#pragma unroll
        for (int j = 0; j < 8; j++) acc[i][j] = 0.0f;

    for (int k0 = 0; k0 < K; k0 += 8) {
        float4 av = *reinterpret_cast<const float4*>(Aptr + k0);
        float4 wv = *reinterpret_cast<const float4*>(Wptr + (size_t)k0 * N);
        __syncthreads();
        As[ak + 0][arow] = av.x;
        As[ak + 1][arow] = av.y;
        As[ak + 2][arow] = av.z;
        As[ak + 3][arow] = av.w;
        *reinterpret_cast<float4*>(&Bs[wrow][wcol]) = wv;
        __syncthreads();
#pragma unroll
        for (int kk = 0; kk < 8; kk++) {
            float4 a0 = *reinterpret_cast<const float4*>(&As[kk][ty * 8]);
            float4 a1 = *reinterpret_cast<const float4*>(&As[kk][ty * 8 + 4]);
            float4 b0 = *reinterpret_cast<const float4*>(&Bs[kk][tx * 8]);
            float4 b1 = *reinterpret_cast<const float4*>(&Bs[kk][tx * 8 + 4]);
            float a[8] = {a0.x, a0.y, a0.z, a0.w, a1.x, a1.y, a1.z, a1.w};
            float b[8] = {b0.x, b0.y, b0.z, b0.w, b1.x, b1.y, b1.z, b1.w};
#pragma unroll
            for (int i = 0; i < 8; i++)
#pragma unroll
                for (int j = 0; j < 8; j++) acc[i][j] += a[i] * b[j];
        }
    }

#pragma unroll
    for (int i = 0; i < 8; i++) {
        int r = row0 + ty * 8 + i;
        float* Crow = C + (size_t)r * N + col0 + tx * 8;
        const float* bp = bias + col0 + tx * 8;
#pragma unroll
        for (int j = 0; j < 8; j++) Crow[j] = acc[i][j] + bp[j];
    }
}

// ---------------- grid barrier (no L1 flush) -----------------------------------
__device__ __forceinline__ void grid_sync(unsigned int target) {
    __syncthreads();
    if (threadIdx.x == 0) {
        asm volatile("red.release.gpu.global.add.u32 [%0], 1;"
                     :: "l"(&g_bar_cnt) : "memory");
        unsigned int v;
        do {
            asm volatile("ld.acquire.gpu.global.u32 %0, [%1];"
                         : "=r"(v) : "l"(&g_bar_cnt) : "memory");
        } while (v < target);
    }
    __syncthreads();
}

// ---------------- persistent GRU recurrence -----------------------------------
// 128 blocks x 256 threads.
// Phase A: bid<64 -> R cols [bid*16,+16); bid>=64 -> U cols [(bid-64)*16,+16)
//   thread: ks=tid>>6 (4-way K split), u=tid&63: n_g=u&3 (4 cols), m_g=u>>2 (4 rows)
// Phase B: bid -> candidate cols [bid*8,+8)
//   thread: ks=tid>>6, u=tid&63: n_g=u&3 (2 cols), m_g=u>>2 (4 rows)
__global__ __launch_bounds__(256, 1) void gru_persistent_kernel(float* __restrict__ states)
{
    __shared__ float hs[2][64][65];   // [buf][batch row][k in chunk], pad 65
    __shared__ float red[2048];       // k-split reduction buffer

    const int tid = threadIdx.x;
    const int bid = blockIdx.x;

    const int ks  = tid >> 6;         // 0..3
    const int u   = tid & 63;
    const int n_g = u & 3;
    const int m_g = u >> 2;           // 0..15

    // copy mapping: thread loads 16 floats of a 64x64 chunk
    const int cf   = tid & 3;         // k-quad group
    const int crow = tid >> 2;        // 0..63

    // phase A
    const int a_gate = bid >> 6;
    const int a_cb   = bid & 63;
    const int a_n0   = a_cb * 16;
    const float* a_W = (a_gate ? g_WuP : g_WrP) + (size_t)a_cb * (H_ * 16);
    const float* a_x = a_gate ? g_xu : g_xr;

    // phase B
    const int b_n0   = bid * 8;
    const float* b_W = g_WhP + (size_t)bid * (H_ * 8);

    unsigned int epoch = 0;

    for (int t = 0; t < T_; t++) {
        const size_t xbase = (size_t)t * B_ * H_;

        // ===================== phase A: gates =====================
        {
            float acc[4][4];
#pragma unroll
            for (int i = 0; i < 4; i++)
#pragma unroll
                for (int j = 0; j < 4; j++) acc[i][j] = 0.0f;

            float4 pre[4];
#pragma unroll
            for (int j = 0; j < 4; j++)
                pre[j] = __ldcg(reinterpret_cast<const float4*>(
                    g_h + (size_t)crow * H_ + cf * 16 + j * 4));
#pragma unroll
            for (int j = 0; j < 4; j++) {
                hs[0][crow][cf * 16 + j * 4 + 0] = pre[j].x;
                hs[0][crow][cf * 16 + j * 4 + 1] = pre[j].y;
                hs[0][crow][cf * 16 + j * 4 + 2] = pre[j].z;
                hs[0][crow][cf * 16 + j * 4 + 3] = pre[j].w;
            }
            __syncthreads();

            for (int c = 0; c < 16; c++) {
                const int buf = c & 1;
                if (c < 15) {
                    const int k0n = (c + 1) * 64;
#pragma unroll
                    for (int j = 0; j < 4; j++)
                        pre[j] = __ldcg(reinterpret_cast<const float4*>(
                            g_h + (size_t)crow * H_ + k0n + cf * 16 + j * 4));
                }
                const float* wb = a_W + (size_t)(c * 64) * 16 + n_g * 4;
#pragma unroll
                for (int kq2 = 0; kq2 < 4; kq2++) {
                    const int kb = (ks + kq2 * 4) * 4;
#pragma unroll
                    for (int kk = 0; kk < 4; kk++) {
                        const int k = kb + kk;
                        float4 w = *reinterpret_cast<const float4*>(wb + (size_t)k * 16);
                        float h0 = hs[buf][m_g * 4 + 0][k];
                        float h1 = hs[buf][m_g * 4 + 1][k];
                        float h2 = hs[buf][m_g * 4 + 2][k];
                        float h3 = hs[buf][m_g * 4 + 3][k];
                        acc[0][0] += h0 * w.x; acc[0][1] += h0 * w.y;
                        acc[0][2] += h0 * w.z; acc[0][3] += h0 * w.w;
                        acc[1][0] += h1 * w.x; acc[1][1] += h1 * w.y;
                        acc[1][2] += h1 * w.z; acc[1][3] += h1 * w.w;
                        acc[2][0] += h2 * w.x; acc[2][1] += h2 * w.y;
                        acc[2][2] += h2 * w.z; acc[2][3] += h2 * w.w;
                        acc[3][0] += h3 * w.x; acc[3][1] += h3 * w.y;
                        acc[3][2] += h3 * w.z; acc[3][3] += h3 * w.w;
                    }
                }
                if (c < 15) {
                    const int nb = buf ^ 1;
#pragma unroll
                    for (int j = 0; j < 4; j++) {
                        hs[nb][crow][cf * 16 + j * 4 + 0] = pre[j].x;
                        hs[nb][crow][cf * 16 + j * 4 + 1] = pre[j].y;
                        hs[nb][crow][cf * 16 + j * 4 + 2] = pre[j].z;
                        hs[nb][crow][cf * 16 + j * 4 + 3] = pre[j].w;
                    }
                }
                __syncthreads();
            }

            // k-split combine: partials ks1,ks3 -> ks0,ks2; then ks2 -> ks0
            if (ks == 1 || ks == 3) {
                float* rb = red + ((ks == 1) ? 0 : 1024);
#pragma unroll
                for (int i = 0; i < 4; i++)
#pragma unroll
                    for (int j = 0; j < 4; j++)
                        rb[(i * 4 + j) * 64 + u] = acc[i][j];
            }
            __syncthreads();
            if (ks == 0 || ks == 2) {
                const float* rb = red + ((ks == 0) ? 0 : 1024);
#pragma unroll
                for (int i = 0; i < 4; i++)
#pragma unroll
                    for (int j = 0; j < 4; j++)
                        acc[i][j] += rb[(i * 4 + j) * 64 + u];
            }
            __syncthreads();
            if (ks == 2) {
#pragma unroll
                for (int i = 0; i < 4; i++)
#pragma unroll
                    for (int j = 0; j < 4; j++)
                        red[(i * 4 + j) * 64 + u] = acc[i][j];
            }
            __syncthreads();
            if (ks == 0) {
                const int nb = a_n0 + n_g * 4;
#pragma unroll
                for (int i = 0; i < 4; i++) {
                    acc[i][0] += red[(i * 4 + 0) * 64 + u];
                    acc[i][1] += red[(i * 4 + 1) * 64 + u];
                    acc[i][2] += red[(i * 4 + 2) * 64 + u];
                    acc[i][3] += red[(i * 4 + 3) * 64 + u];
                    const int r = m_g * 4 + i;
                    float4 x = __ldcg(reinterpret_cast<const float4*>(
                        a_x + xbase + (size_t)r * H_ + nb));
                    float4 s;
                    s.x = 1.0f / (1.0f + __expf(-(acc[i][0] + x.x)));
                    s.y = 1.0f / (1.0f + __expf(-(acc[i][1] + x.y)));
                    s.z = 1.0f / (1.0f + __expf(-(acc[i][2] + x.z)));
                    s.w = 1.0f / (1.0f + __expf(-(acc[i][3] + x.w)));
                    if (a_gate == 0) {
                        float4 h = __ldcg(reinterpret_cast<const float4*>(
                            g_h + (size_t)r * H_ + nb));
                        float4 o = make_float4(h.x * s.x, h.y * s.y, h.z * s.z, h.w * s.w);
                        __stcg(reinterpret_cast<float4*>(g_hR + (size_t)r * H_ + nb), o);
                    } else {
                        __stcg(reinterpret_cast<float4*>(g_U + (size_t)r * H_ + nb), s);
                    }
                }
            }
        }
        epoch++;
        grid_sync(epoch * NBLK);

        // ===================== phase B: candidate + update =====================
        {
            float acc[4][2];
#pragma unroll
            for (int i = 0; i < 4; i++) { acc[i][0] = 0.0f; acc[i][1] = 0.0f; }

            float4 pre[4];
#pragma unroll
            for (int j = 0; j < 4; j++)
                pre[j] = __ldcg(reinterpret_cast<const float4*>(
                    g_hR + (size_t)crow * H_ + cf * 16 + j * 4));
#pragma unroll
            for (int j = 0; j < 4; j++) {
                hs[0][crow][cf * 16 + j * 4 + 0] = pre[j].x;
                hs[0][crow][cf * 16 + j * 4 + 1] = pre[j].y;
                hs[0][crow][cf * 16 + j * 4 + 2] = pre[j].z;
                hs[0][crow][cf * 16 + j * 4 + 3] = pre[j].w;
            }
            __syncthreads();

            for (int c = 0; c < 16; c++) {
                const int buf = c & 1;
                if (c < 15) {
                    const int k0n = (c + 1) * 64;
#pragma unroll
                    for (int j = 0; j < 4; j++)
                        pre[j] = __ldcg(reinterpret_cast<const float4*>(
                            g_hR + (size_t)crow * H_ + k0n + cf * 16 + j * 4));
                }
                const float* wb = b_W + (size_t)(c * 64) * 8 + n_g * 2;
#pragma unroll
                for (int kq2 = 0; kq2 < 4; kq2++) {
                    const int kb = (ks + kq2 * 4) * 4;
#pragma unroll
                    for (int kk = 0; kk < 4; kk++) {
                        const int k = kb + kk;
                        float2 w = *reinterpret_cast<const float2*>(wb + (size_t)k * 8);
                        float h0 = hs[buf][m_g * 4 + 0][k];
                        float h1 = hs[buf][m_g * 4 + 1][k];
                        float h2 = hs[buf][m_g * 4 + 2][k];
                        float h3 = hs[buf][m_g * 4 + 3][k];
                        acc[0][0] += h0 * w.x; acc[0][1] += h0 * w.y;
                        acc[1][0] += h1 * w.x; acc[1][1] += h1 * w.y;
                        acc[2][0] += h2 * w.x; acc[2][1] += h2 * w.y;
                        acc[3][0] += h3 * w.x; acc[3][1] += h3 * w.y;
                    }
                }
                if (c < 15) {
                    const int nb = buf ^ 1;
#pragma unroll
                    for (int j = 0; j < 4; j++) {
                        hs[nb][crow][cf * 16 + j * 4 + 0] = pre[j].x;
                        hs[nb][crow][cf * 16 + j * 4 + 1] = pre[j].y;
                        hs[nb][crow][cf * 16 + j * 4 + 2] = pre[j].z;
                        hs[nb][crow][cf * 16 + j * 4 + 3] = pre[j].w;
                    }
                }
                __syncthreads();
            }

            if (ks == 1 || ks == 3) {
                float* rb = red + ((ks == 1) ? 0 : 1024);
#pragma unroll
                for (int i = 0; i < 4; i++)
#pragma unroll
                    for (int j = 0; j < 2; j++)
                        rb[(i * 2 + j) * 64 + u] = acc[i][j];
            }
            __syncthreads();
            if (ks == 0 || ks == 2) {
                const float* rb = red + ((ks == 0) ? 0 : 1024);
#pragma unroll
                for (int i = 0; i < 4; i++)
#pragma unroll
                    for (int j = 0; j < 2; j++)
                        acc[i][j] += rb[(i * 2 + j) * 64 + u];
            }
            __syncthreads();
            if (ks == 2) {
#pragma unroll
                for (int i = 0; i < 4; i++)
#pragma unroll
                    for (int j = 0; j < 2; j++)
                        red[(i * 2 + j) * 64 + u] = acc[i][j];
            }
            __syncthreads();
            if (ks == 0) {
                const int nb = b_n0 + n_g * 2;
#pragma unroll
                for (int i = 0; i < 4; i++) {
                    acc[i][0] += red[(i * 2 + 0) * 64 + u];
                    acc[i][1] += red[(i * 2 + 1) * 64 + u];
                    const int r = m_g * 4 + i;
                    const size_t off = (size_t)r * H_ + nb;
                    float2 xh = __ldcg(reinterpret_cast<const float2*>(a_x == g_xr ? g_xh + xbase + off : g_xh + xbase + off)); // g_xh always
                    float2 ug = __ldcg(reinterpret_cast<const float2*>(g_U + off));
                    float2 ho = __ldcg(reinterpret_cast<const float2*>(g_h + off));
                    float hc0 = tanhf(acc[i][0] + xh.x);
                    float hc1 = tanhf(acc[i][1] + xh.y);
                    float2 hn;
                    hn.x = ug.x * ho.x + (1.0f - ug.x) * hc0;
                    hn.y = ug.y * ho.y + (1.0f - ug.y) * hc1;
                    __stcg(reinterpret_cast<float2*>(g_h + off), hn);
                    __stcg(reinterpret_cast<float2*>(states + xbase + off), hn);
                }
            }
        }
        epoch++;
        grid_sync(epoch * NBLK);
    }
}

// ---------------- launcher ----------------------------------------------------
extern "C" void kernel_launch(void* const* d_in, const int* in_sizes, int n_in,
                              void* d_out, int out_size)
{
    const float* X    = (const float*)d_in[0];
    const float* W_xr = (const float*)d_in[1];
    const float* W_xu = (const float*)d_in[2];
    const float* W_xh = (const float*)d_in[3];
    const float* W_hr = (const float*)d_in[4];
    const float* W_hu = (const float*)d_in[5];
    const float* W_hh = (const float*)d_in[6];
    const float* b_r  = (const float*)d_in[7];
    const float* b_u  = (const float*)d_in[8];
    const float* b_h  = (const float*)d_in[9];
    const float* W_hq = (const float*)d_in[10];
    const float* b_q  = (const float*)d_in[11];

    float* out     = (float*)d_out;
    float* outputs = out;                        // [T,B,O]
    float* states  = out + (size_t)TB_ * O_;     // [T,B,H]

    void *p_xr, *p_xu, *p_xh, *p_wr, *p_wu, *p_wh;
    cudaGetSymbolAddress(&p_xr, g_xr);
    cudaGetSymbolAddress(&p_xu, g_xu);
    cudaGetSymbolAddress(&p_xh, g_xh);
    cudaGetSymbolAddress(&p_wr, g_WrP);
    cudaGetSymbolAddress(&p_wu, g_WuP);
    cudaGetSymbolAddress(&p_wh, g_WhP);

    init_kernel<<<(B_ * H_ + 255) / 256, 256>>>();

    // repack recurrent weights
    pack16_kernel<<<H_ * H_ / 256, 256>>>(W_hr, (float*)p_wr);
    pack16_kernel<<<H_ * H_ / 256, 256>>>(W_hu, (float*)p_wu);
    pack8_kernel <<<H_ * H_ / 256, 256>>>(W_hh, (float*)p_wh);

    // input projections
    dim3 gproj(H_ / 128, TB_ / 128);
    sgemm_bias_kernel<<<gproj, 256>>>(X, W_xr, b_r, (float*)p_xr, TB_, H_, I_);
    sgemm_bias_kernel<<<gproj, 256>>>(X, W_xu, b_u, (float*)p_xu, TB_, H_, I_);
    sgemm_bias_kernel<<<gproj, 256>>>(X, W_xh, b_h, (float*)p_xh, TB_, H_, I_);

    // recurrence
    gru_persistent_kernel<<<NBLK, 256>>>(states);

    // output projection
    dim3 gout(O_ / 128, TB_ / 128);
    sgemm_bias_kernel<<<gout, 256>>>(states, W_hq, b_q, outputs, TB_, O_, H_);
}

// round 6
// speedup vs baseline: 2.6985x; 1.1427x over previous
#include <cuda_runtime.h>
#include <cuda_bf16.h>
#include <stdint.h>
#include <math.h>

#define T_ 512
#define B_ 64
#define I_ 1024
#define H_ 1024
#define O_ 1024
#define TB_ (T_ * B_)
#define NBLK 128

// ================== scratch (device globals; no allocations) ==================
__device__ float g_xr[TB_ * H_];
__device__ float g_xu[TB_ * H_];
__device__ float g_xh[TB_ * H_];
__device__ float g_h [B_ * H_];
__device__ float g_hR[B_ * H_];
__device__ float g_U [B_ * H_];
__device__ float g_WrP[H_ * H_];
__device__ float g_WuP[H_ * H_];
__device__ float g_WhP[H_ * H_];
__device__ unsigned int g_bar_cnt;

// bf16 split operands (A reused for X and for states)
__device__ __nv_bfloat16 g_Ah[TB_ * H_];           // [m][k] row-major
__device__ __nv_bfloat16 g_Al[TB_ * H_];
__device__ __nv_bfloat16 g_Bh[4][H_ * H_];         // B^T: [n][k] row-major
__device__ __nv_bfloat16 g_Bl[4][H_ * H_];

// ================== init =======================================================
__global__ void init_kernel() {
    int i = blockIdx.x * blockDim.x + threadIdx.x;
    if (i == 0) g_bar_cnt = 0;
    if (i < B_ * H_) g_h[i] = 0.0f;
}

// ================== recurrence weight repack ===================================
__global__ __launch_bounds__(256) void pack16_kernel(
    const float* __restrict__ W, float* __restrict__ P)
{
    int idx = blockIdx.x * 256 + threadIdx.x;
    int k = idx >> 10, n = idx & (H_ - 1);
    P[(((size_t)(n >> 4) * H_ + k) << 4) + (n & 15)] = W[idx];
}
__global__ __launch_bounds__(256) void pack8_kernel(
    const float* __restrict__ W, float* __restrict__ P)
{
    int idx = blockIdx.x * 256 + threadIdx.x;
    int k = idx >> 10, n = idx & (H_ - 1);
    P[(((size_t)(n >> 3) * H_ + k) << 3) + (n & 7)] = W[idx];
}

// ================== bf16 hi/lo split conversions ===============================
// A: [m][k] plain row-major, 4 elements per thread.
__global__ __launch_bounds__(256) void split_convert_A(
    const float* __restrict__ src, __nv_bfloat16* __restrict__ hi,
    __nv_bfloat16* __restrict__ lo)
{
    size_t i4 = ((size_t)blockIdx.x * 256 + threadIdx.x) * 4;
    float4 v = *reinterpret_cast<const float4*>(src + i4);
    float vv[4] = {v.x, v.y, v.z, v.w};
    __align__(8) __nv_bfloat16 hb[4], lb[4];
#pragma unroll
    for (int j = 0; j < 4; j++) {
        __nv_bfloat16 h = __float2bfloat16(vv[j]);
        hb[j] = h;
        lb[j] = __float2bfloat16(vv[j] - __bfloat162float(h));
    }
    *reinterpret_cast<uint2*>(hi + i4) = *reinterpret_cast<const uint2*>(hb);
    *reinterpret_cast<uint2*>(lo + i4) = *reinterpret_cast<const uint2*>(lb);
}

// B: input W [k][n] row-major -> output B^T [n][k] row-major (hi/lo).
__global__ __launch_bounds__(256) void split_convert_B(
    const float* __restrict__ W, __nv_bfloat16* __restrict__ hi,
    __nv_bfloat16* __restrict__ lo)
{
    int idx = blockIdx.x * 256 + threadIdx.x;   // 1M threads
    int k = idx >> 10, n = idx & (H_ - 1);
    float v = W[idx];
    __nv_bfloat16 h = __float2bfloat16(v);
    __nv_bfloat16 l = __float2bfloat16(v - __bfloat162float(h));
    hi[(size_t)n * H_ + k] = h;
    lo[(size_t)n * H_ + k] = l;
}

// ================== PTX helpers ================================================
__device__ __forceinline__ uint32_t s2u(const void* p) {
    uint32_t a;
    asm("{ .reg .u64 t; cvta.to.shared.u64 t, %1; cvt.u32.u64 %0, t; }"
        : "=r"(a) : "l"(p));
    return a;
}
__device__ __forceinline__ void cpa16(uint32_t saddr, const void* g) {
    asm volatile("cp.async.cg.shared.global [%0], [%1], 16;"
                 :: "r"(saddr), "l"(g));
}
__device__ __forceinline__ void ldsm4(uint32_t* r, uint32_t addr) {
    asm volatile("ldmatrix.sync.aligned.m8n8.x4.shared.b16 {%0,%1,%2,%3}, [%4];"
                 : "=r"(r[0]), "=r"(r[1]), "=r"(r[2]), "=r"(r[3]) : "r"(addr));
}
__device__ __forceinline__ void mma16816(float* d, const uint32_t* a,
                                         uint32_t b0, uint32_t b1) {
    asm volatile(
        "mma.sync.aligned.m16n8k16.row.col.f32.bf16.bf16.f32 "
        "{%0,%1,%2,%3}, {%4,%5,%6,%7}, {%8,%9}, {%0,%1,%2,%3};"
        : "+f"(d[0]), "+f"(d[1]), "+f"(d[2]), "+f"(d[3])
        : "r"(a[0]), "r"(a[1]), "r"(a[2]), "r"(a[3]), "r"(b0), "r"(b1));
}

// ================== HMMA GEMM ==================================================
// C[M=32768, N=1024] = Ah@BhT' + Ah@BlT' + Al@BhT' + bias  (B given as [n][k])
// CTA: 128x128 tile, 8 warps (4 m x 2 n), warp tile 32x64, K-chunks of 64.
#define GSTR 72                      // smem row stride (bf16 elems)
#define SMAT (128 * GSTR)            // one matrix buffer (elems)
#define GEMM_SMEM (2 * 4 * SMAT * 2) // bytes = 147456

__global__ __launch_bounds__(256)
void hmma_gemm_kernel(const __nv_bfloat16* __restrict__ Ah,
                      const __nv_bfloat16* __restrict__ Al,
                      const __nv_bfloat16* __restrict__ Bh,
                      const __nv_bfloat16* __restrict__ Bl,
                      const float* __restrict__ bias, float* __restrict__ C)
{
    extern __shared__ __nv_bfloat16 sm[];
    const uint32_t sbase = s2u(sm);

    const int tid  = threadIdx.x;
    const int nt   = blockIdx.x;     // 0..7
    const int mt   = blockIdx.y;     // 0..255
    const int wid  = tid >> 5;
    const int lane = tid & 31;
    const int wm   = wid & 3;        // warp m index (0..3)
    const int wn   = wid >> 2;       // warp n index (0..1)

    const int m0 = mt * 128;
    const int n0 = nt * 128;

    // load mapping: 32 rows x 8 colgroups per pass, 4 passes = 128 rows
    const int lrow = tid >> 3;
    const int lcg  = (tid & 7) * 8;

    // ldmatrix lane offset within a tile (elements)
    const uint32_t loff = (uint32_t)((lane & 15) * GSTR + ((lane >> 4) << 3));

    float acc[2][8][4];
#pragma unroll
    for (int i = 0; i < 2; i++)
#pragma unroll
        for (int j = 0; j < 8; j++)
#pragma unroll
            for (int q = 0; q < 4; q++) acc[i][j][q] = 0.0f;

    // ---- chunk loader (cp.async) ----
    auto load_chunk = [&](int kc, int buf) {
        const __nv_bfloat16* gsrc[4] = {
            Ah + (size_t)(m0 + lrow) * H_ + kc * 64 + lcg,
            Al + (size_t)(m0 + lrow) * H_ + kc * 64 + lcg,
            Bh + (size_t)(n0 + lrow) * H_ + kc * 64 + lcg,
            Bl + (size_t)(n0 + lrow) * H_ + kc * 64 + lcg };
#pragma unroll
        for (int mat = 0; mat < 4; mat++) {
            uint32_t sa = sbase + 2u * ((buf * 4 + mat) * SMAT + lrow * GSTR + lcg);
            const __nv_bfloat16* g = gsrc[mat];
#pragma unroll
            for (int r4 = 0; r4 < 4; r4++)
                cpa16(sa + 2u * (r4 * 32 * GSTR), g + (size_t)(r4 * 32) * H_);
        }
    };

    load_chunk(0, 0);
    asm volatile("cp.async.commit_group;");

    for (int kc = 0; kc < 16; kc++) {
        const int buf = kc & 1;
        if (kc < 15) {
            load_chunk(kc + 1, buf ^ 1);
            asm volatile("cp.async.commit_group;");
            asm volatile("cp.async.wait_group 1;");
        } else {
            asm volatile("cp.async.wait_group 0;");
        }
        __syncthreads();

        const uint32_t bAh = sbase + 2u * ((buf * 4 + 0) * SMAT);
        const uint32_t bAl = sbase + 2u * ((buf * 4 + 1) * SMAT);
        const uint32_t bBh = sbase + 2u * ((buf * 4 + 2) * SMAT);
        const uint32_t bBl = sbase + 2u * ((buf * 4 + 3) * SMAT);

#pragma unroll
        for (int ks = 0; ks < 4; ks++) {
            const uint32_t coff = 2u * (ks * 16) + 2u * loff;
            uint32_t aH[2][4], aL[2][4], bH[4][4], bL[4][4];
#pragma unroll
            for (int im = 0; im < 2; im++) {
                uint32_t ro = 2u * ((wm * 32 + im * 16) * GSTR);
                ldsm4(aH[im], bAh + ro + coff);
                ldsm4(aL[im], bAl + ro + coff);
            }
#pragma unroll
            for (int ib = 0; ib < 4; ib++) {
                uint32_t ro = 2u * ((wn * 64 + ib * 16) * GSTR);
                ldsm4(bH[ib], bBh + ro + coff);
                ldsm4(bL[ib], bBl + ro + coff);
            }
#pragma unroll
            for (int im = 0; im < 2; im++)
#pragma unroll
                for (int ib = 0; ib < 4; ib++)
#pragma unroll
                    for (int hf = 0; hf < 2; hf++) {
                        float* d = acc[im][ib * 2 + hf];
                        mma16816(d, aH[im], bH[ib][hf], bH[ib][hf + 2]);
                        mma16816(d, aH[im], bL[ib][hf], bL[ib][hf + 2]);
                        mma16816(d, aL[im], bH[ib][hf], bH[ib][hf + 2]);
                    }
        }
        __syncthreads();
    }

    // ---- epilogue: bias + store ----
#pragma unroll
    for (int im = 0; im < 2; im++) {
        const int mg = m0 + wm * 32 + im * 16 + (lane >> 2);
#pragma unroll
        for (int nb = 0; nb < 8; nb++) {
            const int ng = n0 + wn * 64 + nb * 8 + (lane & 3) * 2;
            const float bx = bias[ng], by = bias[ng + 1];
            float2 o0, o1;
            o0.x = acc[im][nb][0] + bx; o0.y = acc[im][nb][1] + by;
            o1.x = acc[im][nb][2] + bx; o1.y = acc[im][nb][3] + by;
            *reinterpret_cast<float2*>(C + (size_t)mg * 1024 + ng)       = o0;
            *reinterpret_cast<float2*>(C + (size_t)(mg + 8) * 1024 + ng) = o1;
        }
    }
}

// ================== grid barrier (no L1 flush) =================================
__device__ __forceinline__ void grid_sync(unsigned int target) {
    __syncthreads();
    if (threadIdx.x == 0) {
        asm volatile("red.release.gpu.global.add.u32 [%0], 1;"
                     :: "l"(&g_bar_cnt) : "memory");
        unsigned int v;
        do {
            asm volatile("ld.acquire.gpu.global.u32 %0, [%1];"
                         : "=r"(v) : "l"(&g_bar_cnt) : "memory");
        } while (v < target);
    }
    __syncthreads();
}

// ================== persistent GRU recurrence ==================================
__global__ __launch_bounds__(256, 1) void gru_persistent_kernel(float* __restrict__ states)
{
    __shared__ float hs[2][64][65];
    __shared__ float red[2048];

    const int tid = threadIdx.x;
    const int bid = blockIdx.x;

    const int ks  = tid >> 6;
    const int u   = tid & 63;
    const int n_g = u & 3;
    const int m_g = u >> 2;

    const int cf   = tid & 3;
    const int crow = tid >> 2;

    const int a_gate = bid >> 6;
    const int a_cb   = bid & 63;
    const int a_n0   = a_cb * 16;
    const float* a_W = (a_gate ? g_WuP : g_WrP) + (size_t)a_cb * (H_ * 16);
    const float* a_x = a_gate ? g_xu : g_xr;

    const int b_n0   = bid * 8;
    const float* b_W = g_WhP + (size_t)bid * (H_ * 8);

    unsigned int epoch = 0;

    for (int t = 0; t < T_; t++) {
        const size_t xbase = (size_t)t * B_ * H_;

        // ===================== phase A: gates =====================
        {
            float acc[4][4];
#pragma unroll
            for (int i = 0; i < 4; i++)
#pragma unroll
                for (int j = 0; j < 4; j++) acc[i][j] = 0.0f;

            float4 pre[4];
#pragma unroll
            for (int j = 0; j < 4; j++)
                pre[j] = __ldcg(reinterpret_cast<const float4*>(
                    g_h + (size_t)crow * H_ + cf * 16 + j * 4));
#pragma unroll
            for (int j = 0; j < 4; j++) {
                hs[0][crow][cf * 16 + j * 4 + 0] = pre[j].x;
                hs[0][crow][cf * 16 + j * 4 + 1] = pre[j].y;
                hs[0][crow][cf * 16 + j * 4 + 2] = pre[j].z;
                hs[0][crow][cf * 16 + j * 4 + 3] = pre[j].w;
            }
            __syncthreads();

            for (int c = 0; c < 16; c++) {
                const int buf = c & 1;
                if (c < 15) {
                    const int k0n = (c + 1) * 64;
#pragma unroll
                    for (int j = 0; j < 4; j++)
                        pre[j] = __ldcg(reinterpret_cast<const float4*>(
                            g_h + (size_t)crow * H_ + k0n + cf * 16 + j * 4));
                }
                const float* wb = a_W + (size_t)(c * 64) * 16 + n_g * 4;
#pragma unroll
                for (int kq2 = 0; kq2 < 4; kq2++) {
                    const int kb = (ks + kq2 * 4) * 4;
#pragma unroll
                    for (int kk = 0; kk < 4; kk++) {
                        const int k = kb + kk;
                        float4 w = *reinterpret_cast<const float4*>(wb + (size_t)k * 16);
                        float h0 = hs[buf][m_g * 4 + 0][k];
                        float h1 = hs[buf][m_g * 4 + 1][k];
                        float h2 = hs[buf][m_g * 4 + 2][k];
                        float h3 = hs[buf][m_g * 4 + 3][k];
                        acc[0][0] += h0 * w.x; acc[0][1] += h0 * w.y;
                        acc[0][2] += h0 * w.z; acc[0][3] += h0 * w.w;
                        acc[1][0] += h1 * w.x; acc[1][1] += h1 * w.y;
                        acc[1][2] += h1 * w.z; acc[1][3] += h1 * w.w;
                        acc[2][0] += h2 * w.x; acc[2][1] += h2 * w.y;
                        acc[2][2] += h2 * w.z; acc[2][3] += h2 * w.w;
                        acc[3][0] += h3 * w.x; acc[3][1] += h3 * w.y;
                        acc[3][2] += h3 * w.z; acc[3][3] += h3 * w.w;
                    }
                }
                if (c < 15) {
                    const int nb = buf ^ 1;
#pragma unroll
                    for (int j = 0; j < 4; j++) {
                        hs[nb][crow][cf * 16 + j * 4 + 0] = pre[j].x;
                        hs[nb][crow][cf * 16 + j * 4 + 1] = pre[j].y;
                        hs[nb][crow][cf * 16 + j * 4 + 2] = pre[j].z;
                        hs[nb][crow][cf * 16 + j * 4 + 3] = pre[j].w;
                    }
                }
                __syncthreads();
            }

            if (ks == 1 || ks == 3) {
                float* rb = red + ((ks == 1) ? 0 : 1024);
#pragma unroll
                for (int i = 0; i < 4; i++)
#pragma unroll
                    for (int j = 0; j < 4; j++)
                        rb[(i * 4 + j) * 64 + u] = acc[i][j];
            }
            __syncthreads();
            if (ks == 0 || ks == 2) {
                const float* rb = red + ((ks == 0) ? 0 : 1024);
#pragma unroll
                for (int i = 0; i < 4; i++)
#pragma unroll
                    for (int j = 0; j < 4; j++)
                        acc[i][j] += rb[(i * 4 + j) * 64 + u];
            }
            __syncthreads();
            if (ks == 2) {
#pragma unroll
                for (int i = 0; i < 4; i++)
#pragma unroll
                    for (int j = 0; j < 4; j++)
                        red[(i * 4 + j) * 64 + u] = acc[i][j];
            }
            __syncthreads();
            if (ks == 0) {
                const int nb = a_n0 + n_g * 4;
#pragma unroll
                for (int i = 0; i < 4; i++) {
                    acc[i][0] += red[(i * 4 + 0) * 64 + u];
                    acc[i][1] += red[(i * 4 + 1) * 64 + u];
                    acc[i][2] += red[(i * 4 + 2) * 64 + u];
                    acc[i][3] += red[(i * 4 + 3) * 64 + u];
                    const int r = m_g * 4 + i;
                    float4 x = __ldcg(reinterpret_cast<const float4*>(
                        a_x + xbase + (size_t)r * H_ + nb));
                    float4 s;
                    s.x = 1.0f / (1.0f + __expf(-(acc[i][0] + x.x)));
                    s.y = 1.0f / (1.0f + __expf(-(acc[i][1] + x.y)));
                    s.z = 1.0f / (1.0f + __expf(-(acc[i][2] + x.z)));
                    s.w = 1.0f / (1.0f + __expf(-(acc[i][3] + x.w)));
                    if (a_gate == 0) {
                        float4 h = __ldcg(reinterpret_cast<const float4*>(
                            g_h + (size_t)r * H_ + nb));
                        float4 o = make_float4(h.x * s.x, h.y * s.y, h.z * s.z, h.w * s.w);
                        __stcg(reinterpret_cast<float4*>(g_hR + (size_t)r * H_ + nb), o);
                    } else {
                        __stcg(reinterpret_cast<float4*>(g_U + (size_t)r * H_ + nb), s);
                    }
                }
            }
        }
        epoch++;
        grid_sync(epoch * NBLK);

        // ===================== phase B: candidate + update =====================
        {
            float acc[4][2];
#pragma unroll
            for (int i = 0; i < 4; i++) { acc[i][0] = 0.0f; acc[i][1] = 0.0f; }

            float4 pre[4];
#pragma unroll
            for (int j = 0; j < 4; j++)
                pre[j] = __ldcg(reinterpret_cast<const float4*>(
                    g_hR + (size_t)crow * H_ + cf * 16 + j * 4));
#pragma unroll
            for (int j = 0; j < 4; j++) {
                hs[0][crow][cf * 16 + j * 4 + 0] = pre[j].x;
                hs[0][crow][cf * 16 + j * 4 + 1] = pre[j].y;
                hs[0][crow][cf * 16 + j * 4 + 2] = pre[j].z;
                hs[0][crow][cf * 16 + j * 4 + 3] = pre[j].w;
            }
            __syncthreads();

            for (int c = 0; c < 16; c++) {
                const int buf = c & 1;
                if (c < 15) {
                    const int k0n = (c + 1) * 64;
#pragma unroll
                    for (int j = 0; j < 4; j++)
                        pre[j] = __ldcg(reinterpret_cast<const float4*>(
                            g_hR + (size_t)crow * H_ + k0n + cf * 16 + j * 4));
                }
                const float* wb = b_W + (size_t)(c * 64) * 8 + n_g * 2;
#pragma unroll
                for (int kq2 = 0; kq2 < 4; kq2++) {
                    const int kb = (ks + kq2 * 4) * 4;
#pragma unroll
                    for (int kk = 0; kk < 4; kk++) {
                        const int k = kb + kk;
                        float2 w = *reinterpret_cast<const float2*>(wb + (size_t)k * 8);
                        float h0 = hs[buf][m_g * 4 + 0][k];
                        float h1 = hs[buf][m_g * 4 + 1][k];
                        float h2 = hs[buf][m_g * 4 + 2][k];
                        float h3 = hs[buf][m_g * 4 + 3][k];
                        acc[0][0] += h0 * w.x; acc[0][1] += h0 * w.y;
                        acc[1][0] += h1 * w.x; acc[1][1] += h1 * w.y;
                        acc[2][0] += h2 * w.x; acc[2][1] += h2 * w.y;
                        acc[3][0] += h3 * w.x; acc[3][1] += h3 * w.y;
                    }
                }
                if (c < 15) {
                    const int nb = buf ^ 1;
#pragma unroll
                    for (int j = 0; j < 4; j++) {
                        hs[nb][crow][cf * 16 + j * 4 + 0] = pre[j].x;
                        hs[nb][crow][cf * 16 + j * 4 + 1] = pre[j].y;
                        hs[nb][crow][cf * 16 + j * 4 + 2] = pre[j].z;
                        hs[nb][crow][cf * 16 + j * 4 + 3] = pre[j].w;
                    }
                }
                __syncthreads();
            }

            if (ks == 1 || ks == 3) {
                float* rb = red + ((ks == 1) ? 0 : 1024);
#pragma unroll
                for (int i = 0; i < 4; i++)
#pragma unroll
                    for (int j = 0; j < 2; j++)
                        rb[(i * 2 + j) * 64 + u] = acc[i][j];
            }
            __syncthreads();
            if (ks == 0 || ks == 2) {
                const float* rb = red + ((ks == 0) ? 0 : 1024);
#pragma unroll
                for (int i = 0; i < 4; i++)
#pragma unroll
                    for (int j = 0; j < 2; j++)
                        acc[i][j] += rb[(i * 2 + j) * 64 + u];
            }
            __syncthreads();
            if (ks == 2) {
#pragma unroll
                for (int i = 0; i < 4; i++)
#pragma unroll
                    for (int j = 0; j < 2; j++)
                        red[(i * 2 + j) * 64 + u] = acc[i][j];
            }
            __syncthreads();
            if (ks == 0) {
                const int nb = b_n0 + n_g * 2;
#pragma unroll
                for (int i = 0; i < 4; i++) {
                    acc[i][0] += red[(i * 2 + 0) * 64 + u];
                    acc[i][1] += red[(i * 2 + 1) * 64 + u];
                    const int r = m_g * 4 + i;
                    const size_t off = (size_t)r * H_ + nb;
                    float2 xh = __ldcg(reinterpret_cast<const float2*>(g_xh + xbase + off));
                    float2 ug = __ldcg(reinterpret_cast<const float2*>(g_U + off));
                    float2 ho = __ldcg(reinterpret_cast<const float2*>(g_h + off));
                    float hc0 = tanhf(acc[i][0] + xh.x);
                    float hc1 = tanhf(acc[i][1] + xh.y);
                    float2 hn;
                    hn.x = ug.x * ho.x + (1.0f - ug.x) * hc0;
                    hn.y = ug.y * ho.y + (1.0f - ug.y) * hc1;
                    __stcg(reinterpret_cast<float2*>(g_h + off), hn);
                    __stcg(reinterpret_cast<float2*>(states + xbase + off), hn);
                }
            }
        }
        epoch++;
        grid_sync(epoch * NBLK);
    }
}

// ================== launcher ===================================================
extern "C" void kernel_launch(void* const* d_in, const int* in_sizes, int n_in,
                              void* d_out, int out_size)
{
    const float* X    = (const float*)d_in[0];
    const float* W_xr = (const float*)d_in[1];
    const float* W_xu = (const float*)d_in[2];
    const float* W_xh = (const float*)d_in[3];
    const float* W_hr = (const float*)d_in[4];
    const float* W_hu = (const float*)d_in[5];
    const float* W_hh = (const float*)d_in[6];
    const float* b_r  = (const float*)d_in[7];
    const float* b_u  = (const float*)d_in[8];
    const float* b_h  = (const float*)d_in[9];
    const float* W_hq = (const float*)d_in[10];
    const float* b_q  = (const float*)d_in[11];

    float* out     = (float*)d_out;
    float* outputs = out;                        // [T,B,O]
    float* states  = out + (size_t)TB_ * O_;     // [T,B,H]

    void *p_xr, *p_xu, *p_xh, *p_wr, *p_wu, *p_wh, *p_ah, *p_al, *p_bh, *p_bl;
    cudaGetSymbolAddress(&p_xr, g_xr);
    cudaGetSymbolAddress(&p_xu, g_xu);
    cudaGetSymbolAddress(&p_xh, g_xh);
    cudaGetSymbolAddress(&p_wr, g_WrP);
    cudaGetSymbolAddress(&p_wu, g_WuP);
    cudaGetSymbolAddress(&p_wh, g_WhP);
    cudaGetSymbolAddress(&p_ah, g_Ah);
    cudaGetSymbolAddress(&p_al, g_Al);
    cudaGetSymbolAddress(&p_bh, g_Bh);
    cudaGetSymbolAddress(&p_bl, g_Bl);

    __nv_bfloat16* Ah = (__nv_bfloat16*)p_ah;
    __nv_bfloat16* Al = (__nv_bfloat16*)p_al;
    __nv_bfloat16* Bh = (__nv_bfloat16*)p_bh;
    __nv_bfloat16* Bl = (__nv_bfloat16*)p_bl;

    static int smem_set = 0;
    if (!smem_set) {
        cudaFuncSetAttribute(hmma_gemm_kernel,
                             cudaFuncAttributeMaxDynamicSharedMemorySize, GEMM_SMEM);
        smem_set = 1;
    }

    init_kernel<<<(B_ * H_ + 255) / 256, 256>>>();

    // recurrence weight repack
    pack16_kernel<<<H_ * H_ / 256, 256>>>(W_hr, (float*)p_wr);
    pack16_kernel<<<H_ * H_ / 256, 256>>>(W_hu, (float*)p_wu);
    pack8_kernel <<<H_ * H_ / 256, 256>>>(W_hh, (float*)p_wh);

    // bf16 split conversions
    split_convert_A<<<TB_ * (H_ / 4) / 256, 256>>>(X, Ah, Al);
    split_convert_B<<<H_ * H_ / 256, 256>>>(W_xr, Bh + 0 * (size_t)H_ * H_, Bl + 0 * (size_t)H_ * H_);
    split_convert_B<<<H_ * H_ / 256, 256>>>(W_xu, Bh + 1 * (size_t)H_ * H_, Bl + 1 * (size_t)H_ * H_);
    split_convert_B<<<H_ * H_ / 256, 256>>>(W_xh, Bh + 2 * (size_t)H_ * H_, Bl + 2 * (size_t)H_ * H_);
    split_convert_B<<<H_ * H_ / 256, 256>>>(W_hq, Bh + 3 * (size_t)H_ * H_, Bl + 3 * (size_t)H_ * H_);

    // input projections on tensor cores (mma.sync)
    dim3 gg(O_ / 128, TB_ / 128);
    hmma_gemm_kernel<<<gg, 256, GEMM_SMEM>>>(Ah, Al, Bh + 0 * (size_t)H_ * H_, Bl + 0 * (size_t)H_ * H_, b_r, (float*)p_xr);
    hmma_gemm_kernel<<<gg, 256, GEMM_SMEM>>>(Ah, Al, Bh + 1 * (size_t)H_ * H_, Bl + 1 * (size_t)H_ * H_, b_u, (float*)p_xu);
    hmma_gemm_kernel<<<gg, 256, GEMM_SMEM>>>(Ah, Al, Bh + 2 * (size_t)H_ * H_, Bl + 2 * (size_t)H_ * H_, b_h, (float*)p_xh);

    // recurrence
    gru_persistent_kernel<<<NBLK, 256>>>(states);

    // output projection
    split_convert_A<<<TB_ * (H_ / 4) / 256, 256>>>(states, Ah, Al);
    hmma_gemm_kernel<<<gg, 256, GEMM_SMEM>>>(Ah, Al, Bh + 3 * (size_t)H_ * H_, Bl + 3 * (size_t)H_ * H_, b_q, outputs);
}

// round 7
// speedup vs baseline: 3.6235x; 1.3428x over previous
#include <cuda_runtime.h>
#include <cuda_bf16.h>
#include <stdint.h>
#include <math.h>

#define T_ 512
#define B_ 64
#define I_ 1024
#define H_ 1024
#define O_ 1024
#define TB_ (T_ * B_)
#define NBLK 128

// ================== scratch (device globals; no allocations) ==================
__device__ float g_xr[TB_ * H_];
__device__ float g_xu[TB_ * H_];
__device__ float g_xh[TB_ * H_];
__device__ float g_h [B_ * H_];            // hidden state fp32
__device__ float g_U [B_ * H_];            // update gate fp32
__device__ unsigned int g_bar_cnt;

// bf16 mirrors for tensor-core recurrence
__device__ __nv_bfloat16 g_hh [B_ * H_];   // h hi
__device__ __nv_bfloat16 g_hl [B_ * H_];   // h lo
__device__ __nv_bfloat16 g_hRh[B_ * H_];   // h*R hi
__device__ __nv_bfloat16 g_hRl[B_ * H_];   // h*R lo
__device__ __nv_bfloat16 g_WAh[2 * H_ * H_];  // [W_hr|W_hu] as [n][k], hi
__device__ __nv_bfloat16 g_WAl[2 * H_ * H_];
__device__ __nv_bfloat16 g_WBh[H_ * H_];      // W_hh as [n][k], hi
__device__ __nv_bfloat16 g_WBl[H_ * H_];

// bf16 split operands for projections (A reused for X and states)
__device__ __nv_bfloat16 g_Ah[TB_ * H_];           // [m][k]
__device__ __nv_bfloat16 g_Al[TB_ * H_];
__device__ __nv_bfloat16 g_Bh[4][H_ * H_];         // B^T [n][k]
__device__ __nv_bfloat16 g_Bl[4][H_ * H_];

// ================== init =======================================================
__global__ void init_kernel() {
    int i = blockIdx.x * blockDim.x + threadIdx.x;
    if (i == 0) g_bar_cnt = 0;
    if (i < B_ * H_) {
        g_h[i] = 0.0f;
        g_hh[i] = __float2bfloat16(0.0f);
        g_hl[i] = __float2bfloat16(0.0f);
    }
}

// ================== bf16 hi/lo split conversions ===============================
__global__ __launch_bounds__(256) void split_convert_A(
    const float* __restrict__ src, __nv_bfloat16* __restrict__ hi,
    __nv_bfloat16* __restrict__ lo)
{
    size_t i4 = ((size_t)blockIdx.x * 256 + threadIdx.x) * 4;
    float4 v = *reinterpret_cast<const float4*>(src + i4);
    float vv[4] = {v.x, v.y, v.z, v.w};
    __align__(8) __nv_bfloat16 hb[4], lb[4];
#pragma unroll
    for (int j = 0; j < 4; j++) {
        __nv_bfloat16 h = __float2bfloat16(vv[j]);
        hb[j] = h;
        lb[j] = __float2bfloat16(vv[j] - __bfloat162float(h));
    }
    *reinterpret_cast<uint2*>(hi + i4) = *reinterpret_cast<const uint2*>(hb);
    *reinterpret_cast<uint2*>(lo + i4) = *reinterpret_cast<const uint2*>(lb);
}

// W [k][n] row-major -> out [n][k] bf16 hi/lo
__global__ __launch_bounds__(256) void split_convert_B(
    const float* __restrict__ W, __nv_bfloat16* __restrict__ hi,
    __nv_bfloat16* __restrict__ lo)
{
    int idx = blockIdx.x * 256 + threadIdx.x;
    int k = idx >> 10, n = idx & (H_ - 1);
    float v = W[idx];
    __nv_bfloat16 h = __float2bfloat16(v);
    __nv_bfloat16 l = __float2bfloat16(v - __bfloat162float(h));
    hi[(size_t)n * H_ + k] = h;
    lo[(size_t)n * H_ + k] = l;
}

// ================== PTX helpers ================================================
__device__ __forceinline__ uint32_t s2u(const void* p) {
    uint32_t a;
    asm("{ .reg .u64 t; cvta.to.shared.u64 t, %1; cvt.u32.u64 %0, t; }"
        : "=r"(a) : "l"(p));
    return a;
}
__device__ __forceinline__ void cpa16(uint32_t saddr, const void* g) {
    asm volatile("cp.async.cg.shared.global [%0], [%1], 16;"
                 :: "r"(saddr), "l"(g));
}
__device__ __forceinline__ void ldsm4(uint32_t* r, uint32_t addr) {
    asm volatile("ldmatrix.sync.aligned.m8n8.x4.shared.b16 {%0,%1,%2,%3}, [%4];"
                 : "=r"(r[0]), "=r"(r[1]), "=r"(r[2]), "=r"(r[3]) : "r"(addr));
}
__device__ __forceinline__ void mma16816(float* d, const uint32_t* a,
                                         uint32_t b0, uint32_t b1) {
    asm volatile(
        "mma.sync.aligned.m16n8k16.row.col.f32.bf16.bf16.f32 "
        "{%0,%1,%2,%3}, {%4,%5,%6,%7}, {%8,%9}, {%0,%1,%2,%3};"
        : "+f"(d[0]), "+f"(d[1]), "+f"(d[2]), "+f"(d[3])
        : "r"(a[0]), "r"(a[1]), "r"(a[2]), "r"(a[3]), "r"(b0), "r"(b1));
}
__device__ __forceinline__ uint32_t pack_bf16x2(float v0, float v1) {
    __nv_bfloat16 h0 = __float2bfloat16(v0);
    __nv_bfloat16 h1 = __float2bfloat16(v1);
    unsigned short u0 = *reinterpret_cast<unsigned short*>(&h0);
    unsigned short u1 = *reinterpret_cast<unsigned short*>(&h1);
    return ((uint32_t)u1 << 16) | u0;
}
__device__ __forceinline__ float bf16hi_val(float v) {
    __nv_bfloat16 h = __float2bfloat16(v);
    return __bfloat162float(h);
}

// ================== HMMA GEMM (projections) ====================================
#define GSTR 72
#define SMAT (128 * GSTR)
#define GEMM_SMEM (2 * 4 * SMAT * 2)

__global__ __launch_bounds__(256)
void hmma_gemm_kernel(const __nv_bfloat16* __restrict__ Ah,
                      const __nv_bfloat16* __restrict__ Al,
                      const __nv_bfloat16* __restrict__ Bh,
                      const __nv_bfloat16* __restrict__ Bl,
                      const float* __restrict__ bias, float* __restrict__ C)
{
    extern __shared__ __nv_bfloat16 smx[];
    const uint32_t sbase = s2u(smx);

    const int tid  = threadIdx.x;
    const int nt   = blockIdx.x;
    const int mt   = blockIdx.y;
    const int wid  = tid >> 5;
    const int lane = tid & 31;
    const int wm   = wid & 3;
    const int wn   = wid >> 2;

    const int m0 = mt * 128;
    const int n0 = nt * 128;

    const int lrow = tid >> 3;
    const int lcg  = (tid & 7) * 8;
    const uint32_t loff = (uint32_t)((lane & 15) * GSTR + ((lane >> 4) << 3));

    float acc[2][8][4];
#pragma unroll
    for (int i = 0; i < 2; i++)
#pragma unroll
        for (int j = 0; j < 8; j++)
#pragma unroll
            for (int q = 0; q < 4; q++) acc[i][j][q] = 0.0f;

    auto load_chunk = [&](int kc, int buf) {
        const __nv_bfloat16* gsrc[4] = {
            Ah + (size_t)(m0 + lrow) * H_ + kc * 64 + lcg,
            Al + (size_t)(m0 + lrow) * H_ + kc * 64 + lcg,
            Bh + (size_t)(n0 + lrow) * H_ + kc * 64 + lcg,
            Bl + (size_t)(n0 + lrow) * H_ + kc * 64 + lcg };
#pragma unroll
        for (int mat = 0; mat < 4; mat++) {
            uint32_t sa = sbase + 2u * ((buf * 4 + mat) * SMAT + lrow * GSTR + lcg);
            const __nv_bfloat16* g = gsrc[mat];
#pragma unroll
            for (int r4 = 0; r4 < 4; r4++)
                cpa16(sa + 2u * (r4 * 32 * GSTR), g + (size_t)(r4 * 32) * H_);
        }
    };

    load_chunk(0, 0);
    asm volatile("cp.async.commit_group;");

    for (int kc = 0; kc < 16; kc++) {
        const int buf = kc & 1;
        if (kc < 15) {
            load_chunk(kc + 1, buf ^ 1);
            asm volatile("cp.async.commit_group;");
            asm volatile("cp.async.wait_group 1;");
        } else {
            asm volatile("cp.async.wait_group 0;");
        }
        __syncthreads();

        const uint32_t bAh = sbase + 2u * ((buf * 4 + 0) * SMAT);
        const uint32_t bAl = sbase + 2u * ((buf * 4 + 1) * SMAT);
        const uint32_t bBh = sbase + 2u * ((buf * 4 + 2) * SMAT);
        const uint32_t bBl = sbase + 2u * ((buf * 4 + 3) * SMAT);

#pragma unroll
        for (int ks = 0; ks < 4; ks++) {
            const uint32_t coff = 2u * (ks * 16) + 2u * loff;
            uint32_t aH[2][4], aL[2][4], bH[4][4], bL[4][4];
#pragma unroll
            for (int im = 0; im < 2; im++) {
                uint32_t ro = 2u * ((wm * 32 + im * 16) * GSTR);
                ldsm4(aH[im], bAh + ro + coff);
                ldsm4(aL[im], bAl + ro + coff);
            }
#pragma unroll
            for (int ib = 0; ib < 4; ib++) {
                uint32_t ro = 2u * ((wn * 64 + ib * 16) * GSTR);
                ldsm4(bH[ib], bBh + ro + coff);
                ldsm4(bL[ib], bBl + ro + coff);
            }
#pragma unroll
            for (int im = 0; im < 2; im++)
#pragma unroll
                for (int ib = 0; ib < 4; ib++)
#pragma unroll
                    for (int hf = 0; hf < 2; hf++) {
                        float* d = acc[im][ib * 2 + hf];
                        mma16816(d, aH[im], bH[ib][hf], bH[ib][hf + 2]);
                        mma16816(d, aH[im], bL[ib][hf], bL[ib][hf + 2]);
                        mma16816(d, aL[im], bH[ib][hf], bH[ib][hf + 2]);
                    }
        }
        __syncthreads();
    }

#pragma unroll
    for (int im = 0; im < 2; im++) {
        const int mg = m0 + wm * 32 + im * 16 + (lane >> 2);
#pragma unroll
        for (int nb = 0; nb < 8; nb++) {
            const int ng = n0 + wn * 64 + nb * 8 + (lane & 3) * 2;
            const float bx = bias[ng], by = bias[ng + 1];
            float2 o0, o1;
            o0.x = acc[im][nb][0] + bx; o0.y = acc[im][nb][1] + by;
            o1.x = acc[im][nb][2] + bx; o1.y = acc[im][nb][3] + by;
            *reinterpret_cast<float2*>(C + (size_t)mg * 1024 + ng)       = o0;
            *reinterpret_cast<float2*>(C + (size_t)(mg + 8) * 1024 + ng) = o1;
        }
    }
}

// ================== grid barrier (no L1 flush) =================================
__device__ __forceinline__ void grid_sync(unsigned int target) {
    __syncthreads();
    if (threadIdx.x == 0) {
        asm volatile("red.release.gpu.global.add.u32 [%0], 1;"
                     :: "l"(&g_bar_cnt) : "memory");
        unsigned int v;
        do {
            asm volatile("ld.acquire.gpu.global.u32 %0, [%1];"
                         : "=r"(v) : "l"(&g_bar_cnt) : "memory");
        } while (v < target);
    }
    __syncthreads();
}

// ================== tensor-core persistent GRU recurrence ======================
// smem per buffer: AH(64x72) AL(64x72) BH(16x72) BL(16x72) = 11520 bf16 elems
#define RBUF 11520
#define ROFF_AL 4608
#define ROFF_BH 9216
#define ROFF_BL 10368

__global__ __launch_bounds__(256, 1) void gru_tc_kernel(float* __restrict__ states)
{
    __shared__ __nv_bfloat16 sm[2 * RBUF];
    const uint32_t sbase = s2u(sm);

    const int tid  = threadIdx.x;
    const int bid  = blockIdx.x;
    const int wid  = tid >> 5;
    const int lane = tid & 31;
    const uint32_t loff2 = 2u * (uint32_t)((lane & 15) * GSTR + ((lane >> 4) << 3));

    // staging maps
    const int ar = tid >> 2;             // 0..63
    const int ac = (tid & 3) * 16;       // 0,16,32,48
    const int br = tid >> 3;             // row for B staging
    const int bc = (tid & 7) * 8;

    // phase A identity: blocks 0..63 -> R cols bid*16; 64..127 -> U cols
    const int a_n0 = bid * 16;           // col in combined [R|U] 2048 space
    const __nv_bfloat16* WAh = g_WAh + (size_t)a_n0 * H_;
    const __nv_bfloat16* WAl = g_WAl + (size_t)a_n0 * H_;
    const int a_wm = wid & 3, a_wn = wid >> 2;

    // phase B identity: 8 cols per block, warps 0..3 do mma
    const int b_n0 = bid * 8;
    const __nv_bfloat16* WBh = g_WBh + (size_t)b_n0 * H_;
    const __nv_bfloat16* WBl = g_WBl + (size_t)b_n0 * H_;

    unsigned int epoch = 0;

    for (int t = 0; t < T_; t++) {
        const size_t xbase = (size_t)t * B_ * H_;

        // ======================= phase A: gates ===============================
        {
            float d[4] = {0.f, 0.f, 0.f, 0.f};

            auto stageA = [&](int kc, int buf) {
                const int gc = kc * 64;
                uint32_t sb = sbase + 2u * (buf * RBUF);
                // A = h hi/lo
                uint32_t da = sb + 2u * (ar * GSTR + ac);
                const __nv_bfloat16* s0 = g_hh + (size_t)ar * H_ + gc + ac;
                const __nv_bfloat16* s1 = g_hl + (size_t)ar * H_ + gc + ac;
                cpa16(da, s0); cpa16(da + 16, s0 + 8);
                cpa16(da + 2u * ROFF_AL, s1); cpa16(da + 2u * ROFF_AL + 16, s1 + 8);
                // B = WA rows (16)
                if (tid < 128) {
                    uint32_t db = sb + 2u * (ROFF_BH + br * GSTR + bc);
                    cpa16(db, WAh + (size_t)br * H_ + gc + bc);
                    cpa16(db + 2u * (ROFF_BL - ROFF_BH), WAl + (size_t)br * H_ + gc + bc);
                }
            };

            stageA(0, 0);
            asm volatile("cp.async.commit_group;");

            for (int kc = 0; kc < 16; kc++) {
                const int buf = kc & 1;
                if (kc < 15) {
                    stageA(kc + 1, buf ^ 1);
                    asm volatile("cp.async.commit_group;");
                    asm volatile("cp.async.wait_group 1;");
                } else {
                    asm volatile("cp.async.wait_group 0;");
                }
                __syncthreads();

                const uint32_t sb = sbase + 2u * (buf * RBUF);
#pragma unroll
                for (int ks = 0; ks < 4; ks++) {
                    const uint32_t coff = 2u * (ks * 16) + loff2;
                    uint32_t aH[4], aL[4], bH[4], bL[4];
                    uint32_t ro = 2u * (a_wm * 16 * GSTR);
                    ldsm4(aH, sb + ro + coff);
                    ldsm4(aL, sb + 2u * ROFF_AL + ro + coff);
                    ldsm4(bH, sb + 2u * ROFF_BH + coff);
                    ldsm4(bL, sb + 2u * ROFF_BL + coff);
                    mma16816(d, aH, bH[a_wn], bH[a_wn + 2]);
                    mma16816(d, aH, bL[a_wn], bL[a_wn + 2]);
                    mma16816(d, aL, bH[a_wn], bH[a_wn + 2]);
                }
                __syncthreads();
            }

            // epilogue A
            const int gc = a_n0 + a_wn * 8 + (lane & 3) * 2;
            const int xc = gc & (H_ - 1);
            const float* xp = (bid < 64) ? g_xr : g_xu;
#pragma unroll
            for (int i = 0; i < 2; i++) {
                const int row = a_wm * 16 + (lane >> 2) + i * 8;
                const size_t off = (size_t)row * H_ + xc;
                float2 x = __ldcg(reinterpret_cast<const float2*>(xp + xbase + off));
                float s0 = 1.0f / (1.0f + __expf(-(d[2 * i + 0] + x.x)));
                float s1 = 1.0f / (1.0f + __expf(-(d[2 * i + 1] + x.y)));
                if (bid < 64) {
                    float2 ho = __ldcg(reinterpret_cast<const float2*>(g_h + off));
                    float v0 = ho.x * s0, v1 = ho.y * s1;
                    float h0 = bf16hi_val(v0), h1 = bf16hi_val(v1);
                    __stcg(reinterpret_cast<unsigned int*>(g_hRh) + (off >> 1),
                           pack_bf16x2(v0, v1));
                    __stcg(reinterpret_cast<unsigned int*>(g_hRl) + (off >> 1),
                           pack_bf16x2(v0 - h0, v1 - h1));
                } else {
                    float2 uo = make_float2(s0, s1);
                    __stcg(reinterpret_cast<float2*>(g_U + off), uo);
                }
            }
        }
        epoch++;
        grid_sync(epoch * NBLK);

        // ================= phase B: candidate + update ========================
        {
            float d[4] = {0.f, 0.f, 0.f, 0.f};

            auto stageB = [&](int kc, int buf) {
                const int gc = kc * 64;
                uint32_t sb = sbase + 2u * (buf * RBUF);
                uint32_t da = sb + 2u * (ar * GSTR + ac);
                const __nv_bfloat16* s0 = g_hRh + (size_t)ar * H_ + gc + ac;
                const __nv_bfloat16* s1 = g_hRl + (size_t)ar * H_ + gc + ac;
                cpa16(da, s0); cpa16(da + 16, s0 + 8);
                cpa16(da + 2u * ROFF_AL, s1); cpa16(da + 2u * ROFF_AL + 16, s1 + 8);
                if (tid < 64) {     // 8 valid B rows
                    uint32_t db = sb + 2u * (ROFF_BH + br * GSTR + bc);
                    cpa16(db, WBh + (size_t)br * H_ + gc + bc);
                    cpa16(db + 2u * (ROFF_BL - ROFF_BH), WBl + (size_t)br * H_ + gc + bc);
                }
            };

            stageB(0, 0);
            asm volatile("cp.async.commit_group;");

            for (int kc = 0; kc < 16; kc++) {
                const int buf = kc & 1;
                if (kc < 15) {
                    stageB(kc + 1, buf ^ 1);
                    asm volatile("cp.async.commit_group;");
                    asm volatile("cp.async.wait_group 1;");
                } else {
                    asm volatile("cp.async.wait_group 0;");
                }
                __syncthreads();

                if (wid < 4) {
                    const uint32_t sb = sbase + 2u * (buf * RBUF);
#pragma unroll
                    for (int ks = 0; ks < 4; ks++) {
                        const uint32_t coff = 2u * (ks * 16) + loff2;
                        uint32_t aH[4], aL[4], bH[4], bL[4];
                        uint32_t ro = 2u * (wid * 16 * GSTR);
                        ldsm4(aH, sb + ro + coff);
                        ldsm4(aL, sb + 2u * ROFF_AL + ro + coff);
                        ldsm4(bH, sb + 2u * ROFF_BH + coff);
                        ldsm4(bL, sb + 2u * ROFF_BL + coff);
                        mma16816(d, aH, bH[0], bH[2]);
                        mma16816(d, aH, bL[0], bL[2]);
                        mma16816(d, aL, bH[0], bH[2]);
                    }
                }
                __syncthreads();
            }

            if (wid < 4) {
                const int gc = b_n0 + (lane & 3) * 2;
#pragma unroll
                for (int i = 0; i < 2; i++) {
                    const int row = wid * 16 + (lane >> 2) + i * 8;
                    const size_t off = (size_t)row * H_ + gc;
                    float2 xh = __ldcg(reinterpret_cast<const float2*>(g_xh + xbase + off));
                    float hc0 = tanhf(d[2 * i + 0] + xh.x);
                    float hc1 = tanhf(d[2 * i + 1] + xh.y);
                    float2 u  = __ldcg(reinterpret_cast<const float2*>(g_U + off));
                    float2 ho = __ldcg(reinterpret_cast<const float2*>(g_h + off));
                    float hn0 = u.x * ho.x + (1.0f - u.x) * hc0;
                    float hn1 = u.y * ho.y + (1.0f - u.y) * hc1;
                    __stcg(reinterpret_cast<float2*>(g_h + off), make_float2(hn0, hn1));
                    __stcg(reinterpret_cast<float2*>(states + xbase + off),
                           make_float2(hn0, hn1));
                    float h0 = bf16hi_val(hn0), h1 = bf16hi_val(hn1);
                    __stcg(reinterpret_cast<unsigned int*>(g_hh) + (off >> 1),
                           pack_bf16x2(hn0, hn1));
                    __stcg(reinterpret_cast<unsigned int*>(g_hl) + (off >> 1),
                           pack_bf16x2(hn0 - h0, hn1 - h1));
                }
            }
        }
        epoch++;
        grid_sync(epoch * NBLK);
    }
}

// ================== launcher ===================================================
extern "C" void kernel_launch(void* const* d_in, const int* in_sizes, int n_in,
                              void* d_out, int out_size)
{
    const float* X    = (const float*)d_in[0];
    const float* W_xr = (const float*)d_in[1];
    const float* W_xu = (const float*)d_in[2];
    const float* W_xh = (const float*)d_in[3];
    const float* W_hr = (const float*)d_in[4];
    const float* W_hu = (const float*)d_in[5];
    const float* W_hh = (const float*)d_in[6];
    const float* b_r  = (const float*)d_in[7];
    const float* b_u  = (const float*)d_in[8];
    const float* b_h  = (const float*)d_in[9];
    const float* W_hq = (const float*)d_in[10];
    const float* b_q  = (const float*)d_in[11];

    float* out     = (float*)d_out;
    float* outputs = out;                        // [T,B,O]
    float* states  = out + (size_t)TB_ * O_;     // [T,B,H]

    void *p_xr, *p_xu, *p_xh, *p_ah, *p_al, *p_bh, *p_bl;
    void *p_wah, *p_wal, *p_wbh, *p_wbl;
    cudaGetSymbolAddress(&p_xr, g_xr);
    cudaGetSymbolAddress(&p_xu, g_xu);
    cudaGetSymbolAddress(&p_xh, g_xh);
    cudaGetSymbolAddress(&p_ah, g_Ah);
    cudaGetSymbolAddress(&p_al, g_Al);
    cudaGetSymbolAddress(&p_bh, g_Bh);
    cudaGetSymbolAddress(&p_bl, g_Bl);
    cudaGetSymbolAddress(&p_wah, g_WAh);
    cudaGetSymbolAddress(&p_wal, g_WAl);
    cudaGetSymbolAddress(&p_wbh, g_WBh);
    cudaGetSymbolAddress(&p_wbl, g_WBl);

    __nv_bfloat16* Ah  = (__nv_bfloat16*)p_ah;
    __nv_bfloat16* Al  = (__nv_bfloat16*)p_al;
    __nv_bfloat16* Bh  = (__nv_bfloat16*)p_bh;
    __nv_bfloat16* Bl  = (__nv_bfloat16*)p_bl;
    __nv_bfloat16* WAh = (__nv_bfloat16*)p_wah;
    __nv_bfloat16* WAl = (__nv_bfloat16*)p_wal;
    __nv_bfloat16* WBh = (__nv_bfloat16*)p_wbh;
    __nv_bfloat16* WBl = (__nv_bfloat16*)p_wbl;

    static int smem_set = 0;
    if (!smem_set) {
        cudaFuncSetAttribute(hmma_gemm_kernel,
                             cudaFuncAttributeMaxDynamicSharedMemorySize, GEMM_SMEM);
        smem_set = 1;
    }

    init_kernel<<<(B_ * H_ + 255) / 256, 256>>>();

    // recurrence weights: [R|U] combined + candidate, bf16 hi/lo, [n][k]
    split_convert_B<<<H_ * H_ / 256, 256>>>(W_hr, WAh, WAl);
    split_convert_B<<<H_ * H_ / 256, 256>>>(W_hu, WAh + (size_t)H_ * H_, WAl + (size_t)H_ * H_);
    split_convert_B<<<H_ * H_ / 256, 256>>>(W_hh, WBh, WBl);

    // projection operand conversions
    split_convert_A<<<TB_ * (H_ / 4) / 256, 256>>>(X, Ah, Al);
    split_convert_B<<<H_ * H_ / 256, 256>>>(W_xr, Bh + 0 * (size_t)H_ * H_, Bl + 0 * (size_t)H_ * H_);
    split_convert_B<<<H_ * H_ / 256, 256>>>(W_xu, Bh + 1 * (size_t)H_ * H_, Bl + 1 * (size_t)H_ * H_);
    split_convert_B<<<H_ * H_ / 256, 256>>>(W_xh, Bh + 2 * (size_t)H_ * H_, Bl + 2 * (size_t)H_ * H_);
    split_convert_B<<<H_ * H_ / 256, 256>>>(W_hq, Bh + 3 * (size_t)H_ * H_, Bl + 3 * (size_t)H_ * H_);

    // input projections (HMMA)
    dim3 gg(O_ / 128, TB_ / 128);
    hmma_gemm_kernel<<<gg, 256, GEMM_SMEM>>>(Ah, Al, Bh + 0 * (size_t)H_ * H_, Bl + 0 * (size_t)H_ * H_, b_r, (float*)p_xr);
    hmma_gemm_kernel<<<gg, 256, GEMM_SMEM>>>(Ah, Al, Bh + 1 * (size_t)H_ * H_, Bl + 1 * (size_t)H_ * H_, b_u, (float*)p_xu);
    hmma_gemm_kernel<<<gg, 256, GEMM_SMEM>>>(Ah, Al, Bh + 2 * (size_t)H_ * H_, Bl + 2 * (size_t)H_ * H_, b_h, (float*)p_xh);

    // tensor-core recurrence
    gru_tc_kernel<<<NBLK, 256>>>(states);

    // output projection
    split_convert_A<<<TB_ * (H_ / 4) / 256, 256>>>(states, Ah, Al);
    hmma_gemm_kernel<<<gg, 256, GEMM_SMEM>>>(Ah, Al, Bh + 3 * (size_t)H_ * H_, Bl + 3 * (size_t)H_ * H_, b_q, outputs);
}

// round 8
// speedup vs baseline: 4.4340x; 1.2237x over previous
#include <cuda_runtime.h>
#include <cuda_bf16.h>
#include <stdint.h>
#include <math.h>

#define T_ 512
#define B_ 64
#define I_ 1024
#define H_ 1024
#define O_ 1024
#define TB_ (T_ * B_)
#define NBLK 128

// ================== scratch (device globals; no allocations) ==================
__device__ float g_x[3][TB_ * H_];         // xr, xu, xh projections
__device__ float g_h [B_ * H_];            // hidden state fp32
__device__ float g_U [B_ * H_];            // update gate fp32
__device__ unsigned int g_bar_cnt;

// int8 dual-plane mirrors for tensor-core recurrence
__device__ int8_t g_h1 [B_ * H_];          // h hi plane   (h = (h1*256+h0)*2^-14)
__device__ int8_t g_h0 [B_ * H_];
__device__ int8_t g_hR1[B_ * H_];          // h*R planes
__device__ int8_t g_hR0[B_ * H_];
__device__ int8_t g_w1RU[2 * H_ * H_];     // [W_hr|W_hu] [n][k]  (W = (w1*256+w0)*2^-18)
__device__ int8_t g_w0RU[2 * H_ * H_];
__device__ int8_t g_w1C[H_ * H_];          // W_hh [n][k]
__device__ int8_t g_w0C[H_ * H_];

// bf16 split operands for projections
__device__ __nv_bfloat16 g_Ah[TB_ * H_];   // [m][k]
__device__ __nv_bfloat16 g_Al[TB_ * H_];
__device__ __nv_bfloat16 g_Bh[4][H_ * H_]; // B^T [n][k]: W_xr,W_xu,W_xh,W_hq
__device__ __nv_bfloat16 g_Bl[4][H_ * H_];

// ================== init =======================================================
__global__ void init_kernel() {
    int i = blockIdx.x * blockDim.x + threadIdx.x;
    if (i == 0) g_bar_cnt = 0;
    if (i < B_ * H_) {
        g_h[i] = 0.0f;
        g_h1[i] = 0;
        g_h0[i] = 0;
    }
}

// ================== bf16 hi/lo split conversions ===============================
__global__ __launch_bounds__(256) void split_convert_A(
    const float* __restrict__ src, __nv_bfloat16* __restrict__ hi,
    __nv_bfloat16* __restrict__ lo)
{
    size_t i4 = ((size_t)blockIdx.x * 256 + threadIdx.x) * 4;
    float4 v = *reinterpret_cast<const float4*>(src + i4);
    float vv[4] = {v.x, v.y, v.z, v.w};
    __align__(8) __nv_bfloat16 hb[4], lb[4];
#pragma unroll
    for (int j = 0; j < 4; j++) {
        __nv_bfloat16 h = __float2bfloat16(vv[j]);
        hb[j] = h;
        lb[j] = __float2bfloat16(vv[j] - __bfloat162float(h));
    }
    *reinterpret_cast<uint2*>(hi + i4) = *reinterpret_cast<const uint2*>(hb);
    *reinterpret_cast<uint2*>(lo + i4) = *reinterpret_cast<const uint2*>(lb);
}

__global__ __launch_bounds__(256) void split_convert_B(
    const float* __restrict__ W, __nv_bfloat16* __restrict__ hi,
    __nv_bfloat16* __restrict__ lo)
{
    int idx = blockIdx.x * 256 + threadIdx.x;
    int k = idx >> 10, n = idx & (H_ - 1);
    float v = W[idx];
    __nv_bfloat16 h = __float2bfloat16(v);
    __nv_bfloat16 l = __float2bfloat16(v - __bfloat162float(h));
    hi[(size_t)n * H_ + k] = h;
    lo[(size_t)n * H_ + k] = l;
}

// ================== int8 dual-plane weight quantization ========================
// W [k][n] -> planes [n][k], scale 2^18
__global__ __launch_bounds__(256) void quantW_kernel(
    const float* __restrict__ W, int8_t* __restrict__ p1, int8_t* __restrict__ p0)
{
    int idx = blockIdx.x * 256 + threadIdx.x;
    int k = idx >> 10, n = idx & (H_ - 1);
    float v = W[idx];
    int q = __float2int_rn(v * 262144.0f);
    q = max(-32640, min(32639, q));
    int w1 = (q + 128) >> 8;
    int w0 = q - (w1 << 8);
    p1[(size_t)n * H_ + k] = (int8_t)w1;
    p0[(size_t)n * H_ + k] = (int8_t)w0;
}

// ================== PTX helpers ================================================
__device__ __forceinline__ uint32_t s2u(const void* p) {
    uint32_t a;
    asm("{ .reg .u64 t; cvta.to.shared.u64 t, %1; cvt.u32.u64 %0, t; }"
        : "=r"(a) : "l"(p));
    return a;
}
__device__ __forceinline__ void cpa16(uint32_t saddr, const void* g) {
    asm volatile("cp.async.cg.shared.global [%0], [%1], 16;"
                 :: "r"(saddr), "l"(g));
}
__device__ __forceinline__ void ldsm4(uint32_t* r, uint32_t addr) {
    asm volatile("ldmatrix.sync.aligned.m8n8.x4.shared.b16 {%0,%1,%2,%3}, [%4];"
                 : "=r"(r[0]), "=r"(r[1]), "=r"(r[2]), "=r"(r[3]) : "r"(addr));
}
__device__ __forceinline__ void ldsm2(uint32_t* r, uint32_t addr) {
    asm volatile("ldmatrix.sync.aligned.m8n8.x2.shared.b16 {%0,%1}, [%2];"
                 : "=r"(r[0]), "=r"(r[1]) : "r"(addr));
}
__device__ __forceinline__ void mma16816(float* d, const uint32_t* a,
                                         uint32_t b0, uint32_t b1) {
    asm volatile(
        "mma.sync.aligned.m16n8k16.row.col.f32.bf16.bf16.f32 "
        "{%0,%1,%2,%3}, {%4,%5,%6,%7}, {%8,%9}, {%0,%1,%2,%3};"
        : "+f"(d[0]), "+f"(d[1]), "+f"(d[2]), "+f"(d[3])
        : "r"(a[0]), "r"(a[1]), "r"(a[2]), "r"(a[3]), "r"(b0), "r"(b1));
}
__device__ __forceinline__ void imma32(int* d, const uint32_t* a,
                                       uint32_t b0, uint32_t b1) {
    asm volatile(
        "mma.sync.aligned.m16n8k32.row.col.s32.s8.s8.s32 "
        "{%0,%1,%2,%3}, {%4,%5,%6,%7}, {%8,%9}, {%0,%1,%2,%3};"
        : "+r"(d[0]), "+r"(d[1]), "+r"(d[2]), "+r"(d[3])
        : "r"(a[0]), "r"(a[1]), "r"(a[2]), "r"(a[3]), "r"(b0), "r"(b1));
}

// ================== HMMA GEMM (projections, fused 3-output) ===================
#define GSTR 72
#define SMAT (128 * GSTR)
#define GEMM_SMEM (2 * 4 * SMAT * 2)

struct ProjOut { const float* b[3]; float* c[3]; };

__global__ __launch_bounds__(256)
void hmma_gemm3_kernel(const __nv_bfloat16* __restrict__ Ah,
                       const __nv_bfloat16* __restrict__ Al,
                       const __nv_bfloat16* __restrict__ Bh,
                       const __nv_bfloat16* __restrict__ Bl,
                       ProjOut po)
{
    extern __shared__ __nv_bfloat16 smx[];
    const uint32_t sbase = s2u(smx);

    const int tid  = threadIdx.x;
    const int nt   = blockIdx.x;        // spans fused N
    const int mt   = blockIdx.y;
    const int wid  = tid >> 5;
    const int lane = tid & 31;
    const int wm   = wid & 3;
    const int wn   = wid >> 2;

    const int m0 = mt * 128;
    const int n0 = nt * 128;            // in fused-B space

    const int lrow = tid >> 3;
    const int lcg  = (tid & 7) * 8;
    const uint32_t loff = (uint32_t)((lane & 15) * GSTR + ((lane >> 4) << 3));

    float acc[2][8][4];
#pragma unroll
    for (int i = 0; i < 2; i++)
#pragma unroll
        for (int j = 0; j < 8; j++)
#pragma unroll
            for (int q = 0; q < 4; q++) acc[i][j][q] = 0.0f;

    auto load_chunk = [&](int kc, int buf) {
        const __nv_bfloat16* gsrc[4] = {
            Ah + (size_t)(m0 + lrow) * H_ + kc * 64 + lcg,
            Al + (size_t)(m0 + lrow) * H_ + kc * 64 + lcg,
            Bh + (size_t)(n0 + lrow) * H_ + kc * 64 + lcg,
            Bl + (size_t)(n0 + lrow) * H_ + kc * 64 + lcg };
#pragma unroll
        for (int mat = 0; mat < 4; mat++) {
            uint32_t sa = sbase + 2u * ((buf * 4 + mat) * SMAT + lrow * GSTR + lcg);
            const __nv_bfloat16* g = gsrc[mat];
#pragma unroll
            for (int r4 = 0; r4 < 4; r4++)
                cpa16(sa + 2u * (r4 * 32 * GSTR), g + (size_t)(r4 * 32) * H_);
        }
    };

    load_chunk(0, 0);
    asm volatile("cp.async.commit_group;");

    for (int kc = 0; kc < 16; kc++) {
        const int buf = kc & 1;
        if (kc < 15) {
            load_chunk(kc + 1, buf ^ 1);
            asm volatile("cp.async.commit_group;");
            asm volatile("cp.async.wait_group 1;");
        } else {
            asm volatile("cp.async.wait_group 0;");
        }
        __syncthreads();

        const uint32_t bAh = sbase + 2u * ((buf * 4 + 0) * SMAT);
        const uint32_t bAl = sbase + 2u * ((buf * 4 + 1) * SMAT);
        const uint32_t bBh = sbase + 2u * ((buf * 4 + 2) * SMAT);
        const uint32_t bBl = sbase + 2u * ((buf * 4 + 3) * SMAT);

#pragma unroll
        for (int ks = 0; ks < 4; ks++) {
            const uint32_t coff = 2u * (ks * 16) + 2u * loff;
            uint32_t aH[2][4], aL[2][4], bH[4][4], bL[4][4];
#pragma unroll
            for (int im = 0; im < 2; im++) {
                uint32_t ro = 2u * ((wm * 32 + im * 16) * GSTR);
                ldsm4(aH[im], bAh + ro + coff);
                ldsm4(aL[im], bAl + ro + coff);
            }
#pragma unroll
            for (int ib = 0; ib < 4; ib++) {
                uint32_t ro = 2u * ((wn * 64 + ib * 16) * GSTR);
                ldsm4(bH[ib], bBh + ro + coff);
                ldsm4(bL[ib], bBl + ro + coff);
            }
#pragma unroll
            for (int im = 0; im < 2; im++)
#pragma unroll
                for (int ib = 0; ib < 4; ib++)
#pragma unroll
                    for (int hf = 0; hf < 2; hf++) {
                        float* d = acc[im][ib * 2 + hf];
                        mma16816(d, aH[im], bH[ib][hf], bH[ib][hf + 2]);
                        mma16816(d, aH[im], bL[ib][hf], bL[ib][hf + 2]);
                        mma16816(d, aL[im], bH[ib][hf], bH[ib][hf + 2]);
                    }
        }
        __syncthreads();
    }

    const int sel  = nt >> 3;
    const int ncol = (nt & 7) * 128;
    float* C = po.c[sel];
    const float* bias = po.b[sel];

#pragma unroll
    for (int im = 0; im < 2; im++) {
        const int mg = m0 + wm * 32 + im * 16 + (lane >> 2);
#pragma unroll
        for (int nb = 0; nb < 8; nb++) {
            const int ng = ncol + wn * 64 + nb * 8 + (lane & 3) * 2;
            const float bx = bias[ng], by = bias[ng + 1];
            float2 o0, o1;
            o0.x = acc[im][nb][0] + bx; o0.y = acc[im][nb][1] + by;
            o1.x = acc[im][nb][2] + bx; o1.y = acc[im][nb][3] + by;
            *reinterpret_cast<float2*>(C + (size_t)mg * 1024 + ng)       = o0;
            *reinterpret_cast<float2*>(C + (size_t)(mg + 8) * 1024 + ng) = o1;
        }
    }
}

// ================== grid barrier (no L1 flush) =================================
__device__ __forceinline__ void grid_sync(unsigned int target) {
    __syncthreads();
    if (threadIdx.x == 0) {
        asm volatile("red.release.gpu.global.add.u32 [%0], 1;"
                     :: "l"(&g_bar_cnt) : "memory");
        unsigned int v;
        do {
            asm volatile("ld.acquire.gpu.global.u32 %0, [%1];"
                         : "=r"(v) : "l"(&g_bar_cnt) : "memory");
        } while (v < target);
    }
    __syncthreads();
}

// ================== int8 tensor-core persistent GRU ============================
// s8 tiles, row stride 144 B (auto-rotating, conflict-free for ldmatrix).
// Per buffer: A1(64x144) A0(64x144) B1(16x144) B0(16x144) = 23040 B.
#define QSTR 144
#define QA1 0
#define QA0 9216
#define QB1 18432
#define QB0 20736
#define QBUF 23040
#define S_HI (1.0f / 65536.0f)       // 2^-16
#define S_MID (1.0f / 16777216.0f)   // 2^-24
#define S_LO (1.0f / 4294967296.0f)  // 2^-32

__global__ __launch_bounds__(256, 1) void gru_int8_kernel(float* __restrict__ states)
{
    __shared__ int8_t sm8[2 * QBUF];
    const uint32_t sbase = s2u(sm8);

    const int tid  = threadIdx.x;
    const int bid  = blockIdx.x;
    const int wid  = tid >> 5;
    const int lane = tid & 31;
    const uint32_t loffA  = (uint32_t)((lane & 15) * QSTR + ((lane >> 4) << 4));
    const uint32_t loffB  = (uint32_t)((lane & 7) * QSTR + (((lane >> 3) & 1) << 4));

    // phase A: combined [R|U] 2048-col space, 16 cols per block
    const int a_n0 = bid * 16;
    const int8_t* W1A = g_w1RU + (size_t)a_n0 * H_;
    const int8_t* W0A = g_w0RU + (size_t)a_n0 * H_;
    const int a_wm = wid & 3, a_wn = wid >> 2;

    // phase B: 8 cols per block; warps 0..3 do mma
    const int b_n0 = bid * 8;
    const int8_t* W1B = g_w1C + (size_t)b_n0 * H_;
    const int8_t* W0B = g_w0C + (size_t)b_n0 * H_;

    unsigned int epoch = 0;

    for (int t = 0; t < T_; t++) {
        const size_t xbase = (size_t)t * B_ * H_;

        // ======================= phase A: gates ===============================
        {
            int dhi[4] = {0,0,0,0}, dmid[4] = {0,0,0,0}, dlo[4] = {0,0,0,0};

            auto stageA = [&](int kc, int buf) {
                const int gk = kc * 128;
                const uint32_t sb = sbase + buf * QBUF;
#pragma unroll
                for (int j = 0; j < 2; j++) {
                    int idx = tid + 256 * j;
                    int row = idx >> 3, bo = (idx & 7) * 16;
                    cpa16(sb + QA1 + row * QSTR + bo, g_h1 + row * H_ + gk + bo);
                    cpa16(sb + QA0 + row * QSTR + bo, g_h0 + row * H_ + gk + bo);
                }
                if (tid < 128) {
                    int row = tid >> 3, bo = (tid & 7) * 16;
                    cpa16(sb + QB1 + row * QSTR + bo, W1A + (size_t)row * H_ + gk + bo);
                    cpa16(sb + QB0 + row * QSTR + bo, W0A + (size_t)row * H_ + gk + bo);
                }
            };

            stageA(0, 0);
            asm volatile("cp.async.commit_group;");

            for (int kc = 0; kc < 8; kc++) {
                const int buf = kc & 1;
                if (kc < 7) {
                    stageA(kc + 1, buf ^ 1);
                    asm volatile("cp.async.commit_group;");
                    asm volatile("cp.async.wait_group 1;");
                } else {
                    asm volatile("cp.async.wait_group 0;");
                }
                __syncthreads();

                const uint32_t sb = sbase + buf * QBUF;
#pragma unroll
                for (int ks = 0; ks < 4; ks++) {
                    const uint32_t co = ks * 32;
                    uint32_t a1[4], a0[4], b1[2], b0[2];
                    uint32_t ro = (uint32_t)(a_wm * 16 * QSTR);
                    ldsm4(a1, sb + QA1 + ro + co + loffA);
                    ldsm4(a0, sb + QA0 + ro + co + loffA);
                    uint32_t rb = (uint32_t)(a_wn * 8 * QSTR);
                    ldsm2(b1, sb + QB1 + rb + co + loffB);
                    ldsm2(b0, sb + QB0 + rb + co + loffB);
                    imma32(dhi,  a1, b1[0], b1[1]);
                    imma32(dmid, a1, b0[0], b0[1]);
                    imma32(dmid, a0, b1[0], b1[1]);
                    imma32(dlo,  a0, b0[0], b0[1]);
                }
                __syncthreads();
            }

            // epilogue A
            const int gc = a_n0 + a_wn * 8 + (lane & 3) * 2;
            const int xc = gc & (H_ - 1);
            const float* xp = (bid < 64) ? g_x[0] : g_x[1];
#pragma unroll
            for (int i = 0; i < 2; i++) {
                const int row = a_wm * 16 + (lane >> 2) + i * 8;
                const size_t off = (size_t)row * H_ + xc;
                float2 x = __ldcg(reinterpret_cast<const float2*>(xp + xbase + off));
                float z0 = (float)dhi[2*i+0] * S_HI + (float)dmid[2*i+0] * S_MID
                         + (float)dlo[2*i+0] * S_LO + x.x;
                float z1 = (float)dhi[2*i+1] * S_HI + (float)dmid[2*i+1] * S_MID
                         + (float)dlo[2*i+1] * S_LO + x.y;
                float s0 = 1.0f / (1.0f + __expf(-z0));
                float s1 = 1.0f / (1.0f + __expf(-z1));
                if (bid < 64) {
                    float2 ho = __ldcg(reinterpret_cast<const float2*>(g_h + off));
                    float v0 = ho.x * s0, v1 = ho.y * s1;
                    int q0 = __float2int_rn(v0 * 16384.0f);
                    int q1 = __float2int_rn(v1 * 16384.0f);
                    int p0 = (q0 + 128) >> 8, p1 = (q1 + 128) >> 8;
                    int r0 = q0 - (p0 << 8), r1 = q1 - (p1 << 8);
                    unsigned short hi2 = (unsigned short)((p0 & 0xFF) | ((p1 & 0xFF) << 8));
                    unsigned short lo2 = (unsigned short)((r0 & 0xFF) | ((r1 & 0xFF) << 8));
                    __stcg(reinterpret_cast<unsigned short*>(g_hR1 + off), hi2);
                    __stcg(reinterpret_cast<unsigned short*>(g_hR0 + off), lo2);
                } else {
                    __stcg(reinterpret_cast<float2*>(g_U + off), make_float2(s0, s1));
                }
            }
        }
        epoch++;
        grid_sync(epoch * NBLK);

        // ================= phase B: candidate + update ========================
        {
            int dhi[4] = {0,0,0,0}, dmid[4] = {0,0,0,0}, dlo[4] = {0,0,0,0};

            auto stageB = [&](int kc, int buf) {
                const int gk = kc * 128;
                const uint32_t sb = sbase + buf * QBUF;
#pragma unroll
                for (int j = 0; j < 2; j++) {
                    int idx = tid + 256 * j;
                    int row = idx >> 3, bo = (idx & 7) * 16;
                    cpa16(sb + QA1 + row * QSTR + bo, g_hR1 + row * H_ + gk + bo);
                    cpa16(sb + QA0 + row * QSTR + bo, g_hR0 + row * H_ + gk + bo);
                }
                if (tid < 64) {
                    int row = tid >> 3, bo = (tid & 7) * 16;
                    cpa16(sb + QB1 + row * QSTR + bo, W1B + (size_t)row * H_ + gk + bo);
                    cpa16(sb + QB0 + row * QSTR + bo, W0B + (size_t)row * H_ + gk + bo);
                }
            };

            stageB(0, 0);
            asm volatile("cp.async.commit_group;");

            for (int kc = 0; kc < 8; kc++) {
                const int buf = kc & 1;
                if (kc < 7) {
                    stageB(kc + 1, buf ^ 1);
                    asm volatile("cp.async.commit_group;");
                    asm volatile("cp.async.wait_group 1;");
                } else {
                    asm volatile("cp.async.wait_group 0;");
                }
                __syncthreads();

                if (wid < 4) {
                    const uint32_t sb = sbase + buf * QBUF;
#pragma unroll
                    for (int ks = 0; ks < 4; ks++) {
                        const uint32_t co = ks * 32;
                        uint32_t a1[4], a0[4], b1[2], b0[2];
                        uint32_t ro = (uint32_t)(wid * 16 * QSTR);
                        ldsm4(a1, sb + QA1 + ro + co + loffA);
                        ldsm4(a0, sb + QA0 + ro + co + loffA);
                        ldsm2(b1, sb + QB1 + co + loffB);
                        ldsm2(b0, sb + QB0 + co + loffB);
                        imma32(dhi,  a1, b1[0], b1[1]);
                        imma32(dmid, a1, b0[0], b0[1]);
                        imma32(dmid, a0, b1[0], b1[1]);
                        imma32(dlo,  a0, b0[0], b0[1]);
                    }
                }
                __syncthreads();
            }

            if (wid < 4) {
                const int gc = b_n0 + (lane & 3) * 2;
#pragma unroll
                for (int i = 0; i < 2; i++) {
                    const int row = wid * 16 + (lane >> 2) + i * 8;
                    const size_t off = (size_t)row * H_ + gc;
                    float2 xh = __ldcg(reinterpret_cast<const float2*>(g_x[2] + xbase + off));
                    float z0 = (float)dhi[2*i+0] * S_HI + (float)dmid[2*i+0] * S_MID
                             + (float)dlo[2*i+0] * S_LO + xh.x;
                    float z1 = (float)dhi[2*i+1] * S_HI + (float)dmid[2*i+1] * S_MID
                             + (float)dlo[2*i+1] * S_LO + xh.y;
                    float hc0 = tanhf(z0), hc1 = tanhf(z1);
                    float2 u  = __ldcg(reinterpret_cast<const float2*>(g_U + off));
                    float2 ho = __ldcg(reinterpret_cast<const float2*>(g_h + off));
                    float hn0 = u.x * ho.x + (1.0f - u.x) * hc0;
                    float hn1 = u.y * ho.y + (1.0f - u.y) * hc1;
                    __stcg(reinterpret_cast<float2*>(g_h + off), make_float2(hn0, hn1));
                    __stcg(reinterpret_cast<float2*>(states + xbase + off),
                           make_float2(hn0, hn1));
                    int q0 = __float2int_rn(hn0 * 16384.0f);
                    int q1 = __float2int_rn(hn1 * 16384.0f);
                    int p0 = (q0 + 128) >> 8, p1 = (q1 + 128) >> 8;
                    int r0 = q0 - (p0 << 8), r1 = q1 - (p1 << 8);
                    unsigned short hi2 = (unsigned short)((p0 & 0xFF) | ((p1 & 0xFF) << 8));
                    unsigned short lo2 = (unsigned short)((r0 & 0xFF) | ((r1 & 0xFF) << 8));
                    __stcg(reinterpret_cast<unsigned short*>(g_h1 + off), hi2);
                    __stcg(reinterpret_cast<unsigned short*>(g_h0 + off), lo2);
                }
            }
        }
        epoch++;
        grid_sync(epoch * NBLK);
    }
}

// ================== launcher ===================================================
extern "C" void kernel_launch(void* const* d_in, const int* in_sizes, int n_in,
                              void* d_out, int out_size)
{
    const float* X    = (const float*)d_in[0];
    const float* W_xr = (const float*)d_in[1];
    const float* W_xu = (const float*)d_in[2];
    const float* W_xh = (const float*)d_in[3];
    const float* W_hr = (const float*)d_in[4];
    const float* W_hu = (const float*)d_in[5];
    const float* W_hh = (const float*)d_in[6];
    const float* b_r  = (const float*)d_in[7];
    const float* b_u  = (const float*)d_in[8];
    const float* b_h  = (const float*)d_in[9];
    const float* W_hq = (const float*)d_in[10];
    const float* b_q  = (const float*)d_in[11];

    float* out     = (float*)d_out;
    float* outputs = out;                        // [T,B,O]
    float* states  = out + (size_t)TB_ * O_;     // [T,B,H]

    void *p_x, *p_ah, *p_al, *p_bh, *p_bl;
    void *p_w1ru, *p_w0ru, *p_w1c, *p_w0c;
    cudaGetSymbolAddress(&p_x, g_x);
    cudaGetSymbolAddress(&p_ah, g_Ah);
    cudaGetSymbolAddress(&p_al, g_Al);
    cudaGetSymbolAddress(&p_bh, g_Bh);
    cudaGetSymbolAddress(&p_bl, g_Bl);
    cudaGetSymbolAddress(&p_w1ru, g_w1RU);
    cudaGetSymbolAddress(&p_w0ru, g_w0RU);
    cudaGetSymbolAddress(&p_w1c, g_w1C);
    cudaGetSymbolAddress(&p_w0c, g_w0C);

    float* xbuf = (float*)p_x;
    __nv_bfloat16* Ah = (__nv_bfloat16*)p_ah;
    __nv_bfloat16* Al = (__nv_bfloat16*)p_al;
    __nv_bfloat16* Bh = (__nv_bfloat16*)p_bh;
    __nv_bfloat16* Bl = (__nv_bfloat16*)p_bl;

    static int smem_set = 0;
    if (!smem_set) {
        cudaFuncSetAttribute(hmma_gemm3_kernel,
                             cudaFuncAttributeMaxDynamicSharedMemorySize, GEMM_SMEM);
        smem_set = 1;
    }

    // 0: init
    init_kernel<<<(B_ * H_ + 255) / 256, 256>>>();
    // 1-4: projection operand conversions
    split_convert_A<<<TB_ * (H_ / 4) / 256, 256>>>(X, Ah, Al);
    split_convert_B<<<H_ * H_ / 256, 256>>>(W_xr, Bh + 0 * (size_t)H_ * H_, Bl + 0 * (size_t)H_ * H_);
    split_convert_B<<<H_ * H_ / 256, 256>>>(W_xu, Bh + 1 * (size_t)H_ * H_, Bl + 1 * (size_t)H_ * H_);
    split_convert_B<<<H_ * H_ / 256, 256>>>(W_xh, Bh + 2 * (size_t)H_ * H_, Bl + 2 * (size_t)H_ * H_);
    // 5: fused input projections (profiled launch)
    {
        ProjOut po;
        po.b[0] = b_r; po.b[1] = b_u; po.b[2] = b_h;
        po.c[0] = xbuf; po.c[1] = xbuf + (size_t)TB_ * H_; po.c[2] = xbuf + 2 * (size_t)TB_ * H_;
        dim3 gg(24, TB_ / 128);
        hmma_gemm3_kernel<<<gg, 256, GEMM_SMEM>>>(Ah, Al, Bh, Bl, po);
    }
    // 6-8: recurrence weight quantization
    quantW_kernel<<<H_ * H_ / 256, 256>>>(W_hr, (int8_t*)p_w1ru, (int8_t*)p_w0ru);
    quantW_kernel<<<H_ * H_ / 256, 256>>>(W_hu, (int8_t*)p_w1ru + (size_t)H_ * H_,
                                                (int8_t*)p_w0ru + (size_t)H_ * H_);
    quantW_kernel<<<H_ * H_ / 256, 256>>>(W_hh, (int8_t*)p_w1c, (int8_t*)p_w0c);
    // 9: int8 tensor-core recurrence
    gru_int8_kernel<<<NBLK, 256>>>(states);
    // 10-12: output projection
    split_convert_A<<<TB_ * (H_ / 4) / 256, 256>>>(states, Ah, Al);
    split_convert_B<<<H_ * H_ / 256, 256>>>(W_hq, Bh + 3 * (size_t)H_ * H_, Bl + 3 * (size_t)H_ * H_);
    {
        ProjOut po;
        po.b[0] = b_q; po.b[1] = b_q; po.b[2] = b_q;
        po.c[0] = outputs; po.c[1] = outputs; po.c[2] = outputs;
        dim3 gg(8, TB_ / 128);
        hmma_gemm3_kernel<<<gg, 256, GEMM_SMEM>>>(Ah, Al, Bh + 3 * (size_t)H_ * H_,
                                                  Bl + 3 * (size_t)H_ * H_, po);
    }
}

// round 9
// speedup vs baseline: 4.7021x; 1.0604x over previous
#include <cuda_runtime.h>
#include <cuda_bf16.h>
#include <stdint.h>
#include <math.h>

#define T_ 512
#define B_ 64
#define I_ 1024
#define H_ 1024
#define O_ 1024
#define TB_ (T_ * B_)
#define NBLK 128

// ================== scratch (device globals; no allocations) ==================
__device__ float g_x[3][TB_ * H_];         // xr, xu, xh projections
__device__ float g_h [B_ * H_];            // hidden state fp32
__device__ float g_U [B_ * H_];            // update gate fp32
__device__ unsigned int g_bar_cnt;

// int8 dual-plane mirrors, SWIZZLED layout: addr(r,k) = r*1024 + (((k>>4)^(r&7))<<4) + (k&15)
__device__ int8_t g_h1 [B_ * H_];
__device__ int8_t g_h0 [B_ * H_];
__device__ int8_t g_hR1[B_ * H_];
__device__ int8_t g_hR0[B_ * H_];
__device__ int8_t g_w1RU[2 * H_ * H_];     // [W_hr|W_hu] [n][k] swizzled
__device__ int8_t g_w0RU[2 * H_ * H_];
__device__ int8_t g_w1C[H_ * H_];          // W_hh [n][k] swizzled
__device__ int8_t g_w0C[H_ * H_];

// bf16 split operands for projections
__device__ __nv_bfloat16 g_Ah[TB_ * H_];
__device__ __nv_bfloat16 g_Al[TB_ * H_];
__device__ __nv_bfloat16 g_Bh[4][H_ * H_];
__device__ __nv_bfloat16 g_Bl[4][H_ * H_];

// ================== init =======================================================
__global__ void init_kernel() {
    int i = blockIdx.x * blockDim.x + threadIdx.x;
    if (i == 0) g_bar_cnt = 0;
    if (i < B_ * H_) {
        g_h[i] = 0.0f;
        g_h1[i] = 0;
        g_h0[i] = 0;
    }
}

// ================== bf16 hi/lo split conversions ===============================
__global__ __launch_bounds__(256) void split_convert_A(
    const float* __restrict__ src, __nv_bfloat16* __restrict__ hi,
    __nv_bfloat16* __restrict__ lo)
{
    size_t i4 = ((size_t)blockIdx.x * 256 + threadIdx.x) * 4;
    float4 v = *reinterpret_cast<const float4*>(src + i4);
    float vv[4] = {v.x, v.y, v.z, v.w};
    __align__(8) __nv_bfloat16 hb[4], lb[4];
#pragma unroll
    for (int j = 0; j < 4; j++) {
        __nv_bfloat16 h = __float2bfloat16(vv[j]);
        hb[j] = h;
        lb[j] = __float2bfloat16(vv[j] - __bfloat162float(h));
    }
    *reinterpret_cast<uint2*>(hi + i4) = *reinterpret_cast<const uint2*>(hb);
    *reinterpret_cast<uint2*>(lo + i4) = *reinterpret_cast<const uint2*>(lb);
}

__global__ __launch_bounds__(256) void split_convert_B(
    const float* __restrict__ W, __nv_bfloat16* __restrict__ hi,
    __nv_bfloat16* __restrict__ lo)
{
    int idx = blockIdx.x * 256 + threadIdx.x;
    int k = idx >> 10, n = idx & (H_ - 1);
    float v = W[idx];
    __nv_bfloat16 h = __float2bfloat16(v);
    __nv_bfloat16 l = __float2bfloat16(v - __bfloat162float(h));
    hi[(size_t)n * H_ + k] = h;
    lo[(size_t)n * H_ + k] = l;
}

// ================== int8 dual-plane weight quantization (swizzled) =============
__global__ __launch_bounds__(256) void quantW_kernel(
    const float* __restrict__ W, int8_t* __restrict__ p1, int8_t* __restrict__ p0)
{
    int idx = blockIdx.x * 256 + threadIdx.x;
    int k = idx >> 10, n = idx & (H_ - 1);
    float v = W[idx];
    int q = __float2int_rn(v * 262144.0f);
    q = max(-32640, min(32639, q));
    int w1 = (q + 128) >> 8;
    int w0 = q - (w1 << 8);
    size_t addr = (size_t)n * 1024 + ((((k >> 4) ^ (n & 7)) << 4) | (k & 15));
    p1[addr] = (int8_t)w1;
    p0[addr] = (int8_t)w0;
}

// ================== PTX helpers ================================================
__device__ __forceinline__ uint32_t s2u(const void* p) {
    uint32_t a;
    asm("{ .reg .u64 t; cvta.to.shared.u64 t, %1; cvt.u32.u64 %0, t; }"
        : "=r"(a) : "l"(p));
    return a;
}
__device__ __forceinline__ void cpa16(uint32_t saddr, const void* g) {
    asm volatile("cp.async.cg.shared.global [%0], [%1], 16;"
                 :: "r"(saddr), "l"(g));
}
__device__ __forceinline__ void bulk_g2s(uint32_t saddr, const void* g,
                                         uint32_t bytes, uint32_t mbar) {
    asm volatile(
        "cp.async.bulk.shared::cluster.global.mbarrier::complete_tx::bytes "
        "[%0], [%1], %2, [%3];"
        :: "r"(saddr), "l"(g), "r"(bytes), "r"(mbar) : "memory");
}
__device__ __forceinline__ void ldsm4(uint32_t* r, uint32_t addr) {
    asm volatile("ldmatrix.sync.aligned.m8n8.x4.shared.b16 {%0,%1,%2,%3}, [%4];"
                 : "=r"(r[0]), "=r"(r[1]), "=r"(r[2]), "=r"(r[3]) : "r"(addr));
}
__device__ __forceinline__ void ldsm2(uint32_t* r, uint32_t addr) {
    asm volatile("ldmatrix.sync.aligned.m8n8.x2.shared.b16 {%0,%1}, [%2];"
                 : "=r"(r[0]), "=r"(r[1]) : "r"(addr));
}
__device__ __forceinline__ void mma16816(float* d, const uint32_t* a,
                                         uint32_t b0, uint32_t b1) {
    asm volatile(
        "mma.sync.aligned.m16n8k16.row.col.f32.bf16.bf16.f32 "
        "{%0,%1,%2,%3}, {%4,%5,%6,%7}, {%8,%9}, {%0,%1,%2,%3};"
        : "+f"(d[0]), "+f"(d[1]), "+f"(d[2]), "+f"(d[3])
        : "r"(a[0]), "r"(a[1]), "r"(a[2]), "r"(a[3]), "r"(b0), "r"(b1));
}
__device__ __forceinline__ void imma32(int* d, const uint32_t* a,
                                       uint32_t b0, uint32_t b1) {
    asm volatile(
        "mma.sync.aligned.m16n8k32.row.col.s32.s8.s8.s32 "
        "{%0,%1,%2,%3}, {%4,%5,%6,%7}, {%8,%9}, {%0,%1,%2,%3};"
        : "+r"(d[0]), "+r"(d[1]), "+r"(d[2]), "+r"(d[3])
        : "r"(a[0]), "r"(a[1]), "r"(a[2]), "r"(a[3]), "r"(b0), "r"(b1));
}
#define MBAR_WAIT(mbar, ph) do {                                              \
    asm volatile(                                                             \
        "{\n\t.reg .pred P1;\n\t"                                             \
        "W_%=:\n\t"                                                           \
        "mbarrier.try_wait.parity.acquire.cta.shared::cta.b64 P1, [%0], %1, 0x989680;\n\t" \
        "@P1 bra D_%=;\n\t"                                                   \
        "bra.uni W_%=;\n\t"                                                   \
        "D_%=:\n\t}"                                                          \
        :: "r"(mbar), "r"((unsigned)(ph)) : "memory");                        \
} while (0)

// ================== HMMA GEMM (projections, fused 3-output) ===================
#define GSTR 72
#define SMAT (128 * GSTR)
#define GEMM_SMEM (2 * 4 * SMAT * 2)

struct ProjOut { const float* b[3]; float* c[3]; };

__global__ __launch_bounds__(256)
void hmma_gemm3_kernel(const __nv_bfloat16* __restrict__ Ah,
                       const __nv_bfloat16* __restrict__ Al,
                       const __nv_bfloat16* __restrict__ Bh,
                       const __nv_bfloat16* __restrict__ Bl,
                       ProjOut po)
{
    extern __shared__ __nv_bfloat16 smx[];
    const uint32_t sbase = s2u(smx);

    const int tid  = threadIdx.x;
    const int nt   = blockIdx.x;
    const int mt   = blockIdx.y;
    const int wid  = tid >> 5;
    const int lane = tid & 31;
    const int wm   = wid & 3;
    const int wn   = wid >> 2;

    const int m0 = mt * 128;
    const int n0 = nt * 128;

    const int lrow = tid >> 3;
    const int lcg  = (tid & 7) * 8;
    const uint32_t loff = (uint32_t)((lane & 15) * GSTR + ((lane >> 4) << 3));

    float acc[2][8][4];
#pragma unroll
    for (int i = 0; i < 2; i++)
#pragma unroll
        for (int j = 0; j < 8; j++)
#pragma unroll
            for (int q = 0; q < 4; q++) acc[i][j][q] = 0.0f;

    auto load_chunk = [&](int kc, int buf) {
        const __nv_bfloat16* gsrc[4] = {
            Ah + (size_t)(m0 + lrow) * H_ + kc * 64 + lcg,
            Al + (size_t)(m0 + lrow) * H_ + kc * 64 + lcg,
            Bh + (size_t)(n0 + lrow) * H_ + kc * 64 + lcg,
            Bl + (size_t)(n0 + lrow) * H_ + kc * 64 + lcg };
#pragma unroll
        for (int mat = 0; mat < 4; mat++) {
            uint32_t sa = sbase + 2u * ((buf * 4 + mat) * SMAT + lrow * GSTR + lcg);
            const __nv_bfloat16* g = gsrc[mat];
#pragma unroll
            for (int r4 = 0; r4 < 4; r4++)
                cpa16(sa + 2u * (r4 * 32 * GSTR), g + (size_t)(r4 * 32) * H_);
        }
    };

    load_chunk(0, 0);
    asm volatile("cp.async.commit_group;");

    for (int kc = 0; kc < 16; kc++) {
        const int buf = kc & 1;
        if (kc < 15) {
            load_chunk(kc + 1, buf ^ 1);
            asm volatile("cp.async.commit_group;");
            asm volatile("cp.async.wait_group 1;");
        } else {
            asm volatile("cp.async.wait_group 0;");
        }
        __syncthreads();

        const uint32_t bAh = sbase + 2u * ((buf * 4 + 0) * SMAT);
        const uint32_t bAl = sbase + 2u * ((buf * 4 + 1) * SMAT);
        const uint32_t bBh = sbase + 2u * ((buf * 4 + 2) * SMAT);
        const uint32_t bBl = sbase + 2u * ((buf * 4 + 3) * SMAT);

#pragma unroll
        for (int ks = 0; ks < 4; ks++) {
            const uint32_t coff = 2u * (ks * 16) + 2u * loff;
            uint32_t aH[2][4], aL[2][4], bH[4][4], bL[4][4];
#pragma unroll
            for (int im = 0; im < 2; im++) {
                uint32_t ro = 2u * ((wm * 32 + im * 16) * GSTR);
                ldsm4(aH[im], bAh + ro + coff);
                ldsm4(aL[im], bAl + ro + coff);
            }
#pragma unroll
            for (int ib = 0; ib < 4; ib++) {
                uint32_t ro = 2u * ((wn * 64 + ib * 16) * GSTR);
                ldsm4(bH[ib], bBh + ro + coff);
                ldsm4(bL[ib], bBl + ro + coff);
            }
#pragma unroll
            for (int im = 0; im < 2; im++)
#pragma unroll
                for (int ib = 0; ib < 4; ib++)
#pragma unroll
                    for (int hf = 0; hf < 2; hf++) {
                        float* d = acc[im][ib * 2 + hf];
                        mma16816(d, aH[im], bH[ib][hf], bH[ib][hf + 2]);
                        mma16816(d, aH[im], bL[ib][hf], bL[ib][hf + 2]);
                        mma16816(d, aL[im], bH[ib][hf], bH[ib][hf + 2]);
                    }
        }
        __syncthreads();
    }

    const int sel  = nt >> 3;
    const int ncol = (nt & 7) * 128;
    float* C = po.c[sel];
    const float* bias = po.b[sel];

#pragma unroll
    for (int im = 0; im < 2; im++) {
        const int mg = m0 + wm * 32 + im * 16 + (lane >> 2);
#pragma unroll
        for (int nb = 0; nb < 8; nb++) {
            const int ng = ncol + wn * 64 + nb * 8 + (lane & 3) * 2;
            const float bx = bias[ng], by = bias[ng + 1];
            float2 o0, o1;
            o0.x = acc[im][nb][0] + bx; o0.y = acc[im][nb][1] + by;
            o1.x = acc[im][nb][2] + bx; o1.y = acc[im][nb][3] + by;
            *reinterpret_cast<float2*>(C + (size_t)mg * 1024 + ng)       = o0;
            *reinterpret_cast<float2*>(C + (size_t)(mg + 8) * 1024 + ng) = o1;
        }
    }
}

// ================== grid barrier (no L1 flush) =================================
__device__ __forceinline__ void grid_sync(unsigned int target) {
    __syncthreads();
    if (threadIdx.x == 0) {
        asm volatile("red.release.gpu.global.add.u32 [%0], 1;"
                     :: "l"(&g_bar_cnt) : "memory");
        unsigned int v;
        do {
            asm volatile("ld.acquire.gpu.global.u32 %0, [%1];"
                         : "=r"(v) : "l"(&g_bar_cnt) : "memory");
        } while (v < target);
    }
    __syncthreads();
}

// ================== int8 persistent GRU: bulk staging + resident W =============
// smem (bytes): SW1A 0..16K, SW0A 16K..32K, SW1B 32K..40K, SW0B 40K..48K,
//               SH1 48K..112K, SH0 112K..176K, mbar @176K. Total 176K+64.
#define SW1A 0
#define SW0A 16384
#define SW1B 32768
#define SW0B 40960
#define SH1  49152
#define SH0  114688
#define MBOF 180224
#define RSMEM (180224 + 64)
#define S_HI (1.0f / 65536.0f)
#define S_MID (1.0f / 16777216.0f)
#define S_LO (1.0f / 4294967296.0f)

__global__ __launch_bounds__(256, 1) void gru_int8_kernel(float* __restrict__ states)
{
    extern __shared__ int8_t sm8[];
    const uint32_t sbase = s2u(sm8);
    const uint32_t mbar = sbase + MBOF;

    const int tid  = threadIdx.x;
    const int bid  = blockIdx.x;
    const int wid  = tid >> 5;
    const int lane = tid & 31;

    // phase A: combined [R|U] 2048-col space, 16 cols per block
    const int a_n0 = bid * 16;
    const int a_wm = wid & 3, a_wn = wid >> 2;
    // phase B: 8 cols per block; warps 0..3 do mma
    const int b_n0 = bid * 8;

    // ldmatrix lane identities (rows + 16B-unit select)
    const uint32_t rA_a = (uint32_t)(a_wm * 16 + (lane & 15));
    const uint32_t selA = (uint32_t)(lane >> 4);
    const uint32_t rB_a = (uint32_t)(a_wn * 8 + (lane & 7));
    const uint32_t selB = (uint32_t)((lane >> 3) & 1);
    const uint32_t rA_b = (uint32_t)(wid * 16 + (lane & 15));   // phase B (wid<4)
    const uint32_t rB_b = (uint32_t)(lane & 7);

    // ---- one-time: mbarrier + W tiles into smem (flat copy; swizzle in global)
    if (tid == 0) {
        asm volatile("mbarrier.init.shared.b64 [%0], 1;" :: "r"(mbar) : "memory");
    }
    {
        const int8_t* W1A = g_w1RU + (size_t)a_n0 * 1024;
        const int8_t* W0A = g_w0RU + (size_t)a_n0 * 1024;
        const int8_t* W1B = g_w1C + (size_t)b_n0 * 1024;
        const int8_t* W0B = g_w0C + (size_t)b_n0 * 1024;
        for (int i = tid; i < 1024; i += 256) {   // 16 rows * 64 units
            uint32_t bo = (uint32_t)i * 16;
            cpa16(sbase + SW1A + bo, W1A + (size_t)i * 16);
            cpa16(sbase + SW0A + bo, W0A + (size_t)i * 16);
        }
        for (int i = tid; i < 512; i += 256) {    // 8 rows * 64 units
            uint32_t bo = (uint32_t)i * 16;
            cpa16(sbase + SW1B + bo, W1B + (size_t)i * 16);
            cpa16(sbase + SW0B + bo, W0B + (size_t)i * 16);
        }
        asm volatile("cp.async.commit_group;");
        asm volatile("cp.async.wait_group 0;");
    }
    __syncthreads();

    unsigned int epoch = 0;
    int par = 0;

    for (int t = 0; t < T_; t++) {
        const size_t xbase = (size_t)t * B_ * H_;

        // ======================= phase A: gates ===============================
        {
            if (tid == 0) {
                asm volatile("mbarrier.arrive.expect_tx.shared.b64 _, [%0], %1;"
                             :: "r"(mbar), "r"(131072u) : "memory");
                bulk_g2s(sbase + SH1, g_h1, 65536u, mbar);
                bulk_g2s(sbase + SH0, g_h0, 65536u, mbar);
            }
            MBAR_WAIT(mbar, par);
            par ^= 1;

            int dhi[4] = {0,0,0,0}, dmid[4] = {0,0,0,0}, dlo[4] = {0,0,0,0};
            const uint32_t baseA1 = sbase + SH1 + rA_a * 1024;
            const uint32_t baseA0 = sbase + SH0 + rA_a * 1024;
            const uint32_t baseB1 = sbase + SW1A + rB_a * 1024;
            const uint32_t baseB0 = sbase + SW0A + rB_a * 1024;
            const uint32_t swA = rA_a & 7, swB = rB_a & 7;
#pragma unroll 8
            for (int ks = 0; ks < 32; ks++) {
                const uint32_t uA = (((uint32_t)ks * 2 + selA) ^ swA) << 4;
                const uint32_t uB = (((uint32_t)ks * 2 + selB) ^ swB) << 4;
                uint32_t a1[4], a0[4], b1[2], b0[2];
                ldsm4(a1, baseA1 + uA);
                ldsm4(a0, baseA0 + uA);
                ldsm2(b1, baseB1 + uB);
                ldsm2(b0, baseB0 + uB);
                imma32(dhi,  a1, b1[0], b1[1]);
                imma32(dmid, a1, b0[0], b0[1]);
                imma32(dmid, a0, b1[0], b1[1]);
                imma32(dlo,  a0, b0[0], b0[1]);
            }

            // epilogue A
            const int gc = a_n0 + a_wn * 8 + (lane & 3) * 2;
            const int xc = gc & (H_ - 1);
            const float* xp = (bid < 64) ? g_x[0] : g_x[1];
#pragma unroll
            for (int i = 0; i < 2; i++) {
                const int row = a_wm * 16 + (lane >> 2) + i * 8;
                const size_t off = (size_t)row * H_ + xc;
                float2 x = __ldcg(reinterpret_cast<const float2*>(xp + xbase + off));
                float z0 = (float)dhi[2*i+0] * S_HI + (float)dmid[2*i+0] * S_MID
                         + (float)dlo[2*i+0] * S_LO + x.x;
                float z1 = (float)dhi[2*i+1] * S_HI + (float)dmid[2*i+1] * S_MID
                         + (float)dlo[2*i+1] * S_LO + x.y;
                float s0 = 1.0f / (1.0f + __expf(-z0));
                float s1 = 1.0f / (1.0f + __expf(-z1));
                if (bid < 64) {
                    float2 ho = __ldcg(reinterpret_cast<const float2*>(g_h + off));
                    float v0 = ho.x * s0, v1 = ho.y * s1;
                    int q0 = __float2int_rn(v0 * 16384.0f);
                    int q1 = __float2int_rn(v1 * 16384.0f);
                    int p0 = (q0 + 128) >> 8, p1 = (q1 + 128) >> 8;
                    int r0 = q0 - (p0 << 8), r1 = q1 - (p1 << 8);
                    unsigned short hi2 = (unsigned short)((p0 & 0xFF) | ((p1 & 0xFF) << 8));
                    unsigned short lo2 = (unsigned short)((r0 & 0xFF) | ((r1 & 0xFF) << 8));
                    size_t sa = (size_t)row * 1024 +
                                ((((xc >> 4) ^ (row & 7)) << 4) | (xc & 15));
                    __stcg(reinterpret_cast<unsigned short*>(g_hR1 + sa), hi2);
                    __stcg(reinterpret_cast<unsigned short*>(g_hR0 + sa), lo2);
                } else {
                    __stcg(reinterpret_cast<float2*>(g_U + off), make_float2(s0, s1));
                }
            }
        }
        epoch++;
        grid_sync(epoch * NBLK);

        // ================= phase B: candidate + update ========================
        {
            if (tid == 0) {
                asm volatile("mbarrier.arrive.expect_tx.shared.b64 _, [%0], %1;"
                             :: "r"(mbar), "r"(131072u) : "memory");
                bulk_g2s(sbase + SH1, g_hR1, 65536u, mbar);
                bulk_g2s(sbase + SH0, g_hR0, 65536u, mbar);
            }
            MBAR_WAIT(mbar, par);
            par ^= 1;

            int dhi[4] = {0,0,0,0}, dmid[4] = {0,0,0,0}, dlo[4] = {0,0,0,0};
            if (wid < 4) {
                const uint32_t baseA1 = sbase + SH1 + rA_b * 1024;
                const uint32_t baseA0 = sbase + SH0 + rA_b * 1024;
                const uint32_t baseB1 = sbase + SW1B + rB_b * 1024;
                const uint32_t baseB0 = sbase + SW0B + rB_b * 1024;
                const uint32_t swA = rA_b & 7, swB = rB_b & 7;
#pragma unroll 8
                for (int ks = 0; ks < 32; ks++) {
                    const uint32_t uA = (((uint32_t)ks * 2 + selA) ^ swA) << 4;
                    const uint32_t uB = (((uint32_t)ks * 2 + selB) ^ swB) << 4;
                    uint32_t a1[4], a0[4], b1[2], b0[2];
                    ldsm4(a1, baseA1 + uA);
                    ldsm4(a0, baseA0 + uA);
                    ldsm2(b1, baseB1 + uB);
                    ldsm2(b0, baseB0 + uB);
                    imma32(dhi,  a1, b1[0], b1[1]);
                    imma32(dmid, a1, b0[0], b0[1]);
                    imma32(dmid, a0, b1[0], b1[1]);
                    imma32(dlo,  a0, b0[0], b0[1]);
                }

                const int gc = b_n0 + (lane & 3) * 2;
#pragma unroll
                for (int i = 0; i < 2; i++) {
                    const int row = wid * 16 + (lane >> 2) + i * 8;
                    const size_t off = (size_t)row * H_ + gc;
                    float2 xh = __ldcg(reinterpret_cast<const float2*>(g_x[2] + xbase + off));
                    float z0 = (float)dhi[2*i+0] * S_HI + (float)dmid[2*i+0] * S_MID
                             + (float)dlo[2*i+0] * S_LO + xh.x;
                    float z1 = (float)dhi[2*i+1] * S_HI + (float)dmid[2*i+1] * S_MID
                             + (float)dlo[2*i+1] * S_LO + xh.y;
                    float hc0 = tanhf(z0), hc1 = tanhf(z1);
                    float2 u  = __ldcg(reinterpret_cast<const float2*>(g_U + off));
                    float2 ho = __ldcg(reinterpret_cast<const float2*>(g_h + off));
                    float hn0 = u.x * ho.x + (1.0f - u.x) * hc0;
                    float hn1 = u.y * ho.y + (1.0f - u.y) * hc1;
                    __stcg(reinterpret_cast<float2*>(g_h + off), make_float2(hn0, hn1));
                    __stcg(reinterpret_cast<float2*>(states + xbase + off),
                           make_float2(hn0, hn1));
                    int q0 = __float2int_rn(hn0 * 16384.0f);
                    int q1 = __float2int_rn(hn1 * 16384.0f);
                    int p0 = (q0 + 128) >> 8, p1 = (q1 + 128) >> 8;
                    int r0 = q0 - (p0 << 8), r1 = q1 - (p1 << 8);
                    unsigned short hi2 = (unsigned short)((p0 & 0xFF) | ((p1 & 0xFF) << 8));
                    unsigned short lo2 = (unsigned short)((r0 & 0xFF) | ((r1 & 0xFF) << 8));
                    size_t sa = (size_t)row * 1024 +
                                ((((gc >> 4) ^ (row & 7)) << 4) | (gc & 15));
                    __stcg(reinterpret_cast<unsigned short*>(g_h1 + sa), hi2);
                    __stcg(reinterpret_cast<unsigned short*>(g_h0 + sa), lo2);
                }
            }
        }
        epoch++;
        grid_sync(epoch * NBLK);
    }
}

// ================== launcher ===================================================
extern "C" void kernel_launch(void* const* d_in, const int* in_sizes, int n_in,
                              void* d_out, int out_size)
{
    const float* X    = (const float*)d_in[0];
    const float* W_xr = (const float*)d_in[1];
    const float* W_xu = (const float*)d_in[2];
    const float* W_xh = (const float*)d_in[3];
    const float* W_hr = (const float*)d_in[4];
    const float* W_hu = (const float*)d_in[5];
    const float* W_hh = (const float*)d_in[6];
    const float* b_r  = (const float*)d_in[7];
    const float* b_u  = (const float*)d_in[8];
    const float* b_h  = (const float*)d_in[9];
    const float* W_hq = (const float*)d_in[10];
    const float* b_q  = (const float*)d_in[11];

    float* out     = (float*)d_out;
    float* outputs = out;                        // [T,B,O]
    float* states  = out + (size_t)TB_ * O_;     // [T,B,H]

    void *p_x, *p_ah, *p_al, *p_bh, *p_bl;
    void *p_w1ru, *p_w0ru, *p_w1c, *p_w0c;
    cudaGetSymbolAddress(&p_x, g_x);
    cudaGetSymbolAddress(&p_ah, g_Ah);
    cudaGetSymbolAddress(&p_al, g_Al);
    cudaGetSymbolAddress(&p_bh, g_Bh);
    cudaGetSymbolAddress(&p_bl, g_Bl);
    cudaGetSymbolAddress(&p_w1ru, g_w1RU);
    cudaGetSymbolAddress(&p_w0ru, g_w0RU);
    cudaGetSymbolAddress(&p_w1c, g_w1C);
    cudaGetSymbolAddress(&p_w0c, g_w0C);

    float* xbuf = (float*)p_x;
    __nv_bfloat16* Ah = (__nv_bfloat16*)p_ah;
    __nv_bfloat16* Al = (__nv_bfloat16*)p_al;
    __nv_bfloat16* Bh = (__nv_bfloat16*)p_bh;
    __nv_bfloat16* Bl = (__nv_bfloat16*)p_bl;

    static int smem_set = 0;
    if (!smem_set) {
        cudaFuncSetAttribute(hmma_gemm3_kernel,
                             cudaFuncAttributeMaxDynamicSharedMemorySize, GEMM_SMEM);
        cudaFuncSetAttribute(gru_int8_kernel,
                             cudaFuncAttributeMaxDynamicSharedMemorySize, RSMEM);
        smem_set = 1;
    }

    init_kernel<<<(B_ * H_ + 255) / 256, 256>>>();
    split_convert_A<<<TB_ * (H_ / 4) / 256, 256>>>(X, Ah, Al);
    split_convert_B<<<H_ * H_ / 256, 256>>>(W_xr, Bh + 0 * (size_t)H_ * H_, Bl + 0 * (size_t)H_ * H_);
    split_convert_B<<<H_ * H_ / 256, 256>>>(W_xu, Bh + 1 * (size_t)H_ * H_, Bl + 1 * (size_t)H_ * H_);
    split_convert_B<<<H_ * H_ / 256, 256>>>(W_xh, Bh + 2 * (size_t)H_ * H_, Bl + 2 * (size_t)H_ * H_);
    {
        ProjOut po;
        po.b[0] = b_r; po.b[1] = b_u; po.b[2] = b_h;
        po.c[0] = xbuf; po.c[1] = xbuf + (size_t)TB_ * H_; po.c[2] = xbuf + 2 * (size_t)TB_ * H_;
        dim3 gg(24, TB_ / 128);
        hmma_gemm3_kernel<<<gg, 256, GEMM_SMEM>>>(Ah, Al, Bh, Bl, po);
    }
    quantW_kernel<<<H_ * H_ / 256, 256>>>(W_hr, (int8_t*)p_w1ru, (int8_t*)p_w0ru);
    quantW_kernel<<<H_ * H_ / 256, 256>>>(W_hu, (int8_t*)p_w1ru + (size_t)H_ * H_,
                                                (int8_t*)p_w0ru + (size_t)H_ * H_);
    quantW_kernel<<<H_ * H_ / 256, 256>>>(W_hh, (int8_t*)p_w1c, (int8_t*)p_w0c);
    gru_int8_kernel<<<NBLK, 256, RSMEM>>>(states);
    split_convert_A<<<TB_ * (H_ / 4) / 256, 256>>>(states, Ah, Al);
    split_convert_B<<<H_ * H_ / 256, 256>>>(W_hq, Bh + 3 * (size_t)H_ * H_, Bl + 3 * (size_t)H_ * H_);
    {
        ProjOut po;
        po.b[0] = b_q; po.b[1] = b_q; po.b[2] = b_q;
        po.c[0] = outputs; po.c[1] = outputs; po.c[2] = outputs;
        dim3 gg(8, TB_ / 128);
        hmma_gemm3_kernel<<<gg, 256, GEMM_SMEM>>>(Ah, Al, Bh + 3 * (size_t)H_ * H_,
                                                  Bl + 3 * (size_t)H_ * H_, po);
    }
}

// round 10
// speedup vs baseline: 6.2693x; 1.3333x over previous
#include <cuda_runtime.h>
#include <cuda_bf16.h>
#include <stdint.h>
#include <math.h>

#define T_ 512
#define B_ 64
#define I_ 1024
#define H_ 1024
#define O_ 1024
#define TB_ (T_ * B_)
#define NBLK 128

// ================== scratch (device globals; no allocations) ==================
__device__ float g_x[3][TB_ * H_];         // xr, xu, xh projections
__device__ float g_h [B_ * H_];            // hidden state fp32
__device__ float g_U [B_ * H_];            // update gate fp32
__device__ unsigned int g_bar_cnt;

// int8 dual-plane mirrors, SWIZZLED: addr(r,k) = r*1024 + (((k>>4)^(r&7))<<4) + (k&15)
__device__ int8_t g_h1 [B_ * H_];
__device__ int8_t g_h0 [B_ * H_];
__device__ int8_t g_hR1[B_ * H_];
__device__ int8_t g_hR0[B_ * H_];
__device__ int8_t g_w1RU[2 * H_ * H_];     // [W_hr|W_hu] [n][k] swizzled
__device__ int8_t g_w0RU[2 * H_ * H_];
__device__ int8_t g_w1C[H_ * H_];          // W_hh [n][k] swizzled
__device__ int8_t g_w0C[H_ * H_];

// bf16 split operands for projections (A reused for X and states)
__device__ __nv_bfloat16 g_Ah[TB_ * H_];
__device__ __nv_bfloat16 g_Al[TB_ * H_];
__device__ __nv_bfloat16 g_Bh[4][H_ * H_];
__device__ __nv_bfloat16 g_Bl[4][H_ * H_];

// ================== init =======================================================
__global__ void init_kernel() {
    int i = blockIdx.x * blockDim.x + threadIdx.x;
    if (i == 0) g_bar_cnt = 0;
    if (i < B_ * H_) {
        g_h[i] = 0.0f;
        g_h1[i] = 0;
        g_h0[i] = 0;
    }
}

// ================== conversions ================================================
__global__ __launch_bounds__(256) void split_convert_A(
    const float* __restrict__ src, __nv_bfloat16* __restrict__ hi,
    __nv_bfloat16* __restrict__ lo)
{
    size_t i4 = ((size_t)blockIdx.x * 256 + threadIdx.x) * 4;
    float4 v = *reinterpret_cast<const float4*>(src + i4);
    float vv[4] = {v.x, v.y, v.z, v.w};
    __align__(8) __nv_bfloat16 hb[4], lb[4];
#pragma unroll
    for (int j = 0; j < 4; j++) {
        __nv_bfloat16 h = __float2bfloat16(vv[j]);
        hb[j] = h;
        lb[j] = __float2bfloat16(vv[j] - __bfloat162float(h));
    }
    *reinterpret_cast<uint2*>(hi + i4) = *reinterpret_cast<const uint2*>(hb);
    *reinterpret_cast<uint2*>(lo + i4) = *reinterpret_cast<const uint2*>(lb);
}

// all 4 projection weights -> B^T [n][k] bf16 hi/lo (fused)
__global__ __launch_bounds__(256) void split_convert_B4(
    const float* __restrict__ W0, const float* __restrict__ W1,
    const float* __restrict__ W2, const float* __restrict__ W3)
{
    int which = blockIdx.x >> 12;
    int idx = (blockIdx.x & 4095) * 256 + threadIdx.x;
    const float* W = which == 0 ? W0 : which == 1 ? W1 : which == 2 ? W2 : W3;
    int k = idx >> 10, n = idx & (H_ - 1);
    float v = W[idx];
    __nv_bfloat16 h = __float2bfloat16(v);
    __nv_bfloat16 l = __float2bfloat16(v - __bfloat162float(h));
    g_Bh[which][(size_t)n * H_ + k] = h;
    g_Bl[which][(size_t)n * H_ + k] = l;
}

// recurrence weights: dual-plane int8 quant, swizzled (fused 3 weights)
__global__ __launch_bounds__(256) void quantW3(
    const float* __restrict__ Wr, const float* __restrict__ Wu,
    const float* __restrict__ Wh)
{
    int which = blockIdx.x >> 12;
    int idx = (blockIdx.x & 4095) * 256 + threadIdx.x;
    const float* W = which == 0 ? Wr : which == 1 ? Wu : Wh;
    int8_t* p1 = which == 0 ? g_w1RU : which == 1 ? g_w1RU + (size_t)H_ * H_ : g_w1C;
    int8_t* p0 = which == 0 ? g_w0RU : which == 1 ? g_w0RU + (size_t)H_ * H_ : g_w0C;
    int k = idx >> 10, n = idx & (H_ - 1);
    float v = W[idx];
    int q = __float2int_rn(v * 262144.0f);
    q = max(-32640, min(32639, q));
    int w1 = (q + 128) >> 8;
    int w0 = q - (w1 << 8);
    size_t addr = (size_t)n * 1024 + ((((k >> 4) ^ (n & 7)) << 4) | (k & 15));
    p1[addr] = (int8_t)w1;
    p0[addr] = (int8_t)w0;
}

// ================== PTX helpers ================================================
__device__ __forceinline__ uint32_t s2u(const void* p) {
    uint32_t a;
    asm("{ .reg .u64 t; cvta.to.shared.u64 t, %1; cvt.u32.u64 %0, t; }"
        : "=r"(a) : "l"(p));
    return a;
}
__device__ __forceinline__ void cpa16(uint32_t saddr, const void* g) {
    asm volatile("cp.async.cg.shared.global [%0], [%1], 16;"
                 :: "r"(saddr), "l"(g));
}
__device__ __forceinline__ void bulk_g2s(uint32_t saddr, const void* g,
                                         uint32_t bytes, uint32_t mbar) {
    asm volatile(
        "cp.async.bulk.shared::cluster.global.mbarrier::complete_tx::bytes "
        "[%0], [%1], %2, [%3];"
        :: "r"(saddr), "l"(g), "r"(bytes), "r"(mbar) : "memory");
}
__device__ __forceinline__ void ldsm4(uint32_t* r, uint32_t addr) {
    asm volatile("ldmatrix.sync.aligned.m8n8.x4.shared.b16 {%0,%1,%2,%3}, [%4];"
                 : "=r"(r[0]), "=r"(r[1]), "=r"(r[2]), "=r"(r[3]) : "r"(addr));
}
__device__ __forceinline__ void ldsm2(uint32_t* r, uint32_t addr) {
    asm volatile("ldmatrix.sync.aligned.m8n8.x2.shared.b16 {%0,%1}, [%2];"
                 : "=r"(r[0]), "=r"(r[1]) : "r"(addr));
}
__device__ __forceinline__ void mma16816(float* d, const uint32_t* a,
                                         uint32_t b0, uint32_t b1) {
    asm volatile(
        "mma.sync.aligned.m16n8k16.row.col.f32.bf16.bf16.f32 "
        "{%0,%1,%2,%3}, {%4,%5,%6,%7}, {%8,%9}, {%0,%1,%2,%3};"
        : "+f"(d[0]), "+f"(d[1]), "+f"(d[2]), "+f"(d[3])
        : "r"(a[0]), "r"(a[1]), "r"(a[2]), "r"(a[3]), "r"(b0), "r"(b1));
}
__device__ __forceinline__ void imma32(int* d, const uint32_t* a,
                                       uint32_t b0, uint32_t b1) {
    asm volatile(
        "mma.sync.aligned.m16n8k32.row.col.s32.s8.s8.s32 "
        "{%0,%1,%2,%3}, {%4,%5,%6,%7}, {%8,%9}, {%0,%1,%2,%3};"
        : "+r"(d[0]), "+r"(d[1]), "+r"(d[2]), "+r"(d[3])
        : "r"(a[0]), "r"(a[1]), "r"(a[2]), "r"(a[3]), "r"(b0), "r"(b1));
}
#define MBAR_WAIT(mbar, ph) do {                                              \
    asm volatile(                                                             \
        "{\n\t.reg .pred P1;\n\t"                                             \
        "W_%=:\n\t"                                                           \
        "mbarrier.try_wait.parity.acquire.cta.shared::cta.b64 P1, [%0], %1, 0x989680;\n\t" \
        "@P1 bra D_%=;\n\t"                                                   \
        "bra.uni W_%=;\n\t"                                                   \
        "D_%=:\n\t}"                                                          \
        :: "r"(mbar), "r"((unsigned)(ph)) : "memory");                        \
} while (0)

// ================== HMMA GEMM (projections, fused 3-output) ===================
#define GSTR 72
#define SMAT (128 * GSTR)
#define GEMM_SMEM (2 * 4 * SMAT * 2)

struct ProjOut { const float* b[3]; float* c[3]; };

__global__ __launch_bounds__(256)
void hmma_gemm3_kernel(const __nv_bfloat16* __restrict__ Ah,
                       const __nv_bfloat16* __restrict__ Al,
                       const __nv_bfloat16* __restrict__ Bh,
                       const __nv_bfloat16* __restrict__ Bl,
                       ProjOut po)
{
    extern __shared__ __nv_bfloat16 smx[];
    const uint32_t sbase = s2u(smx);

    const int tid  = threadIdx.x;
    const int nt   = blockIdx.x;
    const int mt   = blockIdx.y;
    const int wid  = tid >> 5;
    const int lane = tid & 31;
    const int wm   = wid & 3;
    const int wn   = wid >> 2;

    const int m0 = mt * 128;
    const int n0 = nt * 128;

    const int lrow = tid >> 3;
    const int lcg  = (tid & 7) * 8;
    const uint32_t loff = (uint32_t)((lane & 15) * GSTR + ((lane >> 4) << 3));

    float acc[2][8][4];
#pragma unroll
    for (int i = 0; i < 2; i++)
#pragma unroll
        for (int j = 0; j < 8; j++)
#pragma unroll
            for (int q = 0; q < 4; q++) acc[i][j][q] = 0.0f;

    auto load_chunk = [&](int kc, int buf) {
        const __nv_bfloat16* gsrc[4] = {
            Ah + (size_t)(m0 + lrow) * H_ + kc * 64 + lcg,
            Al + (size_t)(m0 + lrow) * H_ + kc * 64 + lcg,
            Bh + (size_t)(n0 + lrow) * H_ + kc * 64 + lcg,
            Bl + (size_t)(n0 + lrow) * H_ + kc * 64 + lcg };
#pragma unroll
        for (int mat = 0; mat < 4; mat++) {
            uint32_t sa = sbase + 2u * ((buf * 4 + mat) * SMAT + lrow * GSTR + lcg);
            const __nv_bfloat16* g = gsrc[mat];
#pragma unroll
            for (int r4 = 0; r4 < 4; r4++)
                cpa16(sa + 2u * (r4 * 32 * GSTR), g + (size_t)(r4 * 32) * H_);
        }
    };

    load_chunk(0, 0);
    asm volatile("cp.async.commit_group;");

    for (int kc = 0; kc < 16; kc++) {
        const int buf = kc & 1;
        if (kc < 15) {
            load_chunk(kc + 1, buf ^ 1);
            asm volatile("cp.async.commit_group;");
            asm volatile("cp.async.wait_group 1;");
        } else {
            asm volatile("cp.async.wait_group 0;");
        }
        __syncthreads();

        const uint32_t bAh = sbase + 2u * ((buf * 4 + 0) * SMAT);
        const uint32_t bAl = sbase + 2u * ((buf * 4 + 1) * SMAT);
        const uint32_t bBh = sbase + 2u * ((buf * 4 + 2) * SMAT);
        const uint32_t bBl = sbase + 2u * ((buf * 4 + 3) * SMAT);

#pragma unroll
        for (int ks = 0; ks < 4; ks++) {
            const uint32_t coff = 2u * (ks * 16) + 2u * loff;
            uint32_t aH[2][4], aL[2][4], bH[4][4], bL[4][4];
#pragma unroll
            for (int im = 0; im < 2; im++) {
                uint32_t ro = 2u * ((wm * 32 + im * 16) * GSTR);
                ldsm4(aH[im], bAh + ro + coff);
                ldsm4(aL[im], bAl + ro + coff);
            }
#pragma unroll
            for (int ib = 0; ib < 4; ib++) {
                uint32_t ro = 2u * ((wn * 64 + ib * 16) * GSTR);
                ldsm4(bH[ib], bBh + ro + coff);
                ldsm4(bL[ib], bBl + ro + coff);
            }
#pragma unroll
            for (int im = 0; im < 2; im++)
#pragma unroll
                for (int ib = 0; ib < 4; ib++)
#pragma unroll
                    for (int hf = 0; hf < 2; hf++) {
                        float* d = acc[im][ib * 2 + hf];
                        mma16816(d, aH[im], bH[ib][hf], bH[ib][hf + 2]);
                        mma16816(d, aH[im], bL[ib][hf], bL[ib][hf + 2]);
                        mma16816(d, aL[im], bH[ib][hf], bH[ib][hf + 2]);
                    }
        }
        __syncthreads();
    }

    const int sel  = nt >> 3;
    const int ncol = (nt & 7) * 128;
    float* C = po.c[sel];
    const float* bias = po.b[sel];

#pragma unroll
    for (int im = 0; im < 2; im++) {
        const int mg = m0 + wm * 32 + im * 16 + (lane >> 2);
#pragma unroll
        for (int nb = 0; nb < 8; nb++) {
            const int ng = ncol + wn * 64 + nb * 8 + (lane & 3) * 2;
            const float bx = bias[ng], by = bias[ng + 1];
            float2 o0, o1;
            o0.x = acc[im][nb][0] + bx; o0.y = acc[im][nb][1] + by;
            o1.x = acc[im][nb][2] + bx; o1.y = acc[im][nb][3] + by;
            *reinterpret_cast<float2*>(C + (size_t)mg * 1024 + ng)       = o0;
            *reinterpret_cast<float2*>(C + (size_t)(mg + 8) * 1024 + ng) = o1;
        }
    }
}

// ================== grid barrier (no L1 flush) =================================
__device__ __forceinline__ void grid_sync(unsigned int target) {
    __syncthreads();
    if (threadIdx.x == 0) {
        asm volatile("red.release.gpu.global.add.u32 [%0], 1;"
                     :: "l"(&g_bar_cnt) : "memory");
        unsigned int v;
        do {
            asm volatile("ld.acquire.gpu.global.u32 %0, [%1];"
                         : "=r"(v) : "l"(&g_bar_cnt) : "memory");
        } while (v < target);
    }
    __syncthreads();
}

// ================== int8 persistent GRU (pipelined chunks, resident W) =========
#define SW1A 0
#define SW0A 16384
#define SW1B 32768
#define SW0B 40960
#define SH1  49152
#define SH0  114688
#define MBOF 180224
#define REDOF 180288
#define RSMEM (180288 + 6144)
#define S_HI (1.0f / 65536.0f)
#define S_MID (1.0f / 16777216.0f)

__global__ __launch_bounds__(256, 1) void gru_int8_kernel(float* __restrict__ states)
{
    extern __shared__ int8_t sm8[];
    const uint32_t sbase = s2u(sm8);
    const uint32_t mb0 = sbase + MBOF;

    const int tid  = threadIdx.x;
    const int bid  = blockIdx.x;
    const int wid  = tid >> 5;
    const int lane = tid & 31;

    const int a_n0 = bid * 16;                 // phase A: [R|U] combined cols
    const int a_wm = wid & 3, a_wn = wid >> 2;
    const int b_n0 = bid * 8;                  // phase B

    const uint32_t rA_a = (uint32_t)(a_wm * 16 + (lane & 15));
    const uint32_t selA = (uint32_t)(lane >> 4);
    const uint32_t rB_a = (uint32_t)(a_wn * 8 + (lane & 7));
    const uint32_t selB = (uint32_t)((lane >> 3) & 1);
    const uint32_t rA_b = (uint32_t)((wid & 3) * 16 + (lane & 15));
    const uint32_t rB_b = (uint32_t)(lane & 7);

    // ---- one-time: mbarriers + resident W tiles ----
    if (tid == 0) {
#pragma unroll
        for (int c = 0; c < 4; c++)
            asm volatile("mbarrier.init.shared.b64 [%0], 1;"
                         :: "r"(mb0 + c * 8) : "memory");
    }
    {
        const int8_t* W1A = g_w1RU + (size_t)a_n0 * 1024;
        const int8_t* W0A = g_w0RU + (size_t)a_n0 * 1024;
        const int8_t* W1B = g_w1C + (size_t)b_n0 * 1024;
        const int8_t* W0B = g_w0C + (size_t)b_n0 * 1024;
        for (int i = tid; i < 1024; i += 256) {
            uint32_t bo = (uint32_t)i * 16;
            cpa16(sbase + SW1A + bo, W1A + (size_t)i * 16);
            cpa16(sbase + SW0A + bo, W0A + (size_t)i * 16);
        }
        for (int i = tid; i < 512; i += 256) {
            uint32_t bo = (uint32_t)i * 16;
            cpa16(sbase + SW1B + bo, W1B + (size_t)i * 16);
            cpa16(sbase + SW0B + bo, W0B + (size_t)i * 16);
        }
        asm volatile("cp.async.commit_group;");
        asm volatile("cp.async.wait_group 0;");
    }
    __syncthreads();

    unsigned int epoch = 0;
    int par = 0;

    for (int t = 0; t < T_; t++) {
        const size_t xbase = (size_t)t * B_ * H_;

        // ======================= phase A: gates ===============================
        {
            // prefetch epilogue inputs (L2 latency hides behind copy+MMA)
            const int gc = a_n0 + a_wn * 8 + (lane & 3) * 2;
            const int xc = gc & (H_ - 1);
            const float* xp = (bid < 64) ? g_x[0] : g_x[1];
            float2 xv[2], hv[2];
#pragma unroll
            for (int i = 0; i < 2; i++) {
                const int row = a_wm * 16 + (lane >> 2) + i * 8;
                const size_t off = (size_t)row * H_ + xc;
                xv[i] = __ldcg(reinterpret_cast<const float2*>(xp + xbase + off));
                if (bid < 64)
                    hv[i] = __ldcg(reinterpret_cast<const float2*>(g_h + off));
            }
            // stage h planes in 4 row-chunks
            if (tid == 0) {
#pragma unroll
                for (int c = 0; c < 4; c++) {
                    asm volatile("mbarrier.arrive.expect_tx.shared.b64 _, [%0], %1;"
                                 :: "r"(mb0 + c * 8), "r"(32768u) : "memory");
                    bulk_g2s(sbase + SH1 + c * 16384, g_h1 + c * 16384, 16384u, mb0 + c * 8);
                    bulk_g2s(sbase + SH0 + c * 16384, g_h0 + c * 16384, 16384u, mb0 + c * 8);
                }
            }
            MBAR_WAIT(mb0 + a_wm * 8, par);

            int dhi[4] = {0,0,0,0}, dmA[4] = {0,0,0,0}, dmB[4] = {0,0,0,0};
            const uint32_t baseA1 = sbase + SH1 + rA_a * 1024;
            const uint32_t baseA0 = sbase + SH0 + rA_a * 1024;
            const uint32_t baseB1 = sbase + SW1A + rB_a * 1024;
            const uint32_t baseB0 = sbase + SW0A + rB_a * 1024;
            const uint32_t swA = rA_a & 7, swB = rB_a & 7;
#pragma unroll 8
            for (int ks = 0; ks < 32; ks++) {
                const uint32_t uA = (((uint32_t)ks * 2 + selA) ^ swA) << 4;
                const uint32_t uB = (((uint32_t)ks * 2 + selB) ^ swB) << 4;
                uint32_t a1[4], a0[4], b1[2], b0[2];
                ldsm4(a1, baseA1 + uA);
                ldsm4(a0, baseA0 + uA);
                ldsm2(b1, baseB1 + uB);
                ldsm2(b0, baseB0 + uB);
                imma32(dhi, a1, b1[0], b1[1]);
                imma32(dmA, a1, b0[0], b0[1]);
                imma32(dmB, a0, b1[0], b1[1]);
            }

            // epilogue A
#pragma unroll
            for (int i = 0; i < 2; i++) {
                const int row = a_wm * 16 + (lane >> 2) + i * 8;
                const size_t off = (size_t)row * H_ + xc;
                float z0 = (float)dhi[2*i+0] * S_HI
                         + (float)(dmA[2*i+0] + dmB[2*i+0]) * S_MID + xv[i].x;
                float z1 = (float)dhi[2*i+1] * S_HI
                         + (float)(dmA[2*i+1] + dmB[2*i+1]) * S_MID + xv[i].y;
                float s0 = 1.0f / (1.0f + __expf(-z0));
                float s1 = 1.0f / (1.0f + __expf(-z1));
                if (bid < 64) {
                    float v0 = hv[i].x * s0, v1 = hv[i].y * s1;
                    int q0 = __float2int_rn(v0 * 16384.0f);
                    int q1 = __float2int_rn(v1 * 16384.0f);
                    int p0 = (q0 + 128) >> 8, p1 = (q1 + 128) >> 8;
                    int r0 = q0 - (p0 << 8), r1 = q1 - (p1 << 8);
                    unsigned short hi2 = (unsigned short)((p0 & 0xFF) | ((p1 & 0xFF) << 8));
                    unsigned short lo2 = (unsigned short)((r0 & 0xFF) | ((r1 & 0xFF) << 8));
                    size_t sa = (size_t)row * 1024 +
                                ((((xc >> 4) ^ (row & 7)) << 4) | (xc & 15));
                    __stcg(reinterpret_cast<unsigned short*>(g_hR1 + sa), hi2);
                    __stcg(reinterpret_cast<unsigned short*>(g_hR0 + sa), lo2);
                } else {
                    __stcg(reinterpret_cast<float2*>(g_U + off), make_float2(s0, s1));
                }
            }
        }
        par ^= 1;
        epoch++;
        grid_sync(epoch * NBLK);

        // ================= phase B: candidate + update ========================
        {
            // prefetch epilogue inputs (warps 0-3 own the epilogue)
            const int gc = b_n0 + (lane & 3) * 2;
            float2 xv[2], uv[2], hv[2];
            if (wid < 4) {
#pragma unroll
                for (int i = 0; i < 2; i++) {
                    const int row = wid * 16 + (lane >> 2) + i * 8;
                    const size_t off = (size_t)row * H_ + gc;
                    xv[i] = __ldcg(reinterpret_cast<const float2*>(g_x[2] + xbase + off));
                    uv[i] = __ldcg(reinterpret_cast<const float2*>(g_U + off));
                    hv[i] = __ldcg(reinterpret_cast<const float2*>(g_h + off));
                }
            }
            if (tid == 0) {
#pragma unroll
                for (int c = 0; c < 4; c++) {
                    asm volatile("mbarrier.arrive.expect_tx.shared.b64 _, [%0], %1;"
                                 :: "r"(mb0 + c * 8), "r"(32768u) : "memory");
                    bulk_g2s(sbase + SH1 + c * 16384, g_hR1 + c * 16384, 16384u, mb0 + c * 8);
                    bulk_g2s(sbase + SH0 + c * 16384, g_hR0 + c * 16384, 16384u, mb0 + c * 8);
                }
            }
            MBAR_WAIT(mb0 + (wid & 3) * 8, par);

            int dhi[4] = {0,0,0,0}, dmA[4] = {0,0,0,0}, dmB[4] = {0,0,0,0};
            {
                const uint32_t baseA1 = sbase + SH1 + rA_b * 1024;
                const uint32_t baseA0 = sbase + SH0 + rA_b * 1024;
                const uint32_t baseB1 = sbase + SW1B + rB_b * 1024;
                const uint32_t baseB0 = sbase + SW0B + rB_b * 1024;
                const uint32_t swA = rA_b & 7, swB = rB_b & 7;
                const int ks0 = (wid >> 2) * 16;   // K-split across warp halves
#pragma unroll 8
                for (int ks = ks0; ks < ks0 + 16; ks++) {
                    const uint32_t uA = (((uint32_t)ks * 2 + selA) ^ swA) << 4;
                    const uint32_t uB = (((uint32_t)ks * 2 + selB) ^ swB) << 4;
                    uint32_t a1[4], a0[4], b1[2], b0[2];
                    ldsm4(a1, baseA1 + uA);
                    ldsm4(a0, baseA0 + uA);
                    ldsm2(b1, baseB1 + uB);
                    ldsm2(b0, baseB0 + uB);
                    imma32(dhi, a1, b1[0], b1[1]);
                    imma32(dmA, a1, b0[0], b0[1]);
                    imma32(dmB, a0, b1[0], b1[1]);
                }
            }
            // reduce upper-K partials (warps 4-7) into lower warps
            if (wid >= 4) {
                int* rb = reinterpret_cast<int*>(sm8 + REDOF)
                          + (((wid - 4) * 32 + lane) * 12);
#pragma unroll
                for (int j = 0; j < 4; j++) { rb[j] = dhi[j]; rb[4 + j] = dmA[j]; rb[8 + j] = dmB[j]; }
            }
            __syncthreads();
            if (wid < 4) {
                const int* rb = reinterpret_cast<const int*>(sm8 + REDOF)
                                + ((wid * 32 + lane) * 12);
#pragma unroll
                for (int j = 0; j < 4; j++) { dhi[j] += rb[j]; dmA[j] += rb[4 + j]; dmB[j] += rb[8 + j]; }

#pragma unroll
                for (int i = 0; i < 2; i++) {
                    const int row = wid * 16 + (lane >> 2) + i * 8;
                    const size_t off = (size_t)row * H_ + gc;
                    float z0 = (float)dhi[2*i+0] * S_HI
                             + (float)(dmA[2*i+0] + dmB[2*i+0]) * S_MID + xv[i].x;
                    float z1 = (float)dhi[2*i+1] * S_HI
                             + (float)(dmA[2*i+1] + dmB[2*i+1]) * S_MID + xv[i].y;
                    float hc0 = tanhf(z0), hc1 = tanhf(z1);
                    float hn0 = uv[i].x * hv[i].x + (1.0f - uv[i].x) * hc0;
                    float hn1 = uv[i].y * hv[i].y + (1.0f - uv[i].y) * hc1;
                    __stcg(reinterpret_cast<float2*>(g_h + off), make_float2(hn0, hn1));
                    __stcg(reinterpret_cast<float2*>(states + xbase + off),
                           make_float2(hn0, hn1));
                    // bf16 split of states for the output projection
                    __nv_bfloat16 b0 = __float2bfloat16(hn0);
                    __nv_bfloat16 b1 = __float2bfloat16(hn1);
                    unsigned short u0 = *reinterpret_cast<unsigned short*>(&b0);
                    unsigned short u1 = *reinterpret_cast<unsigned short*>(&b1);
                    __nv_bfloat16 l0 = __float2bfloat16(hn0 - __bfloat162float(b0));
                    __nv_bfloat16 l1 = __float2bfloat16(hn1 - __bfloat162float(b1));
                    unsigned short v0 = *reinterpret_cast<unsigned short*>(&l0);
                    unsigned short v1 = *reinterpret_cast<unsigned short*>(&l1);
                    __stcg(reinterpret_cast<unsigned int*>(g_Ah + xbase + off),
                           ((unsigned)u1 << 16) | u0);
                    __stcg(reinterpret_cast<unsigned int*>(g_Al + xbase + off),
                           ((unsigned)v1 << 16) | v0);
                    // int8 dual-plane h for next step
                    int q0 = __float2int_rn(hn0 * 16384.0f);
                    int q1 = __float2int_rn(hn1 * 16384.0f);
                    int p0 = (q0 + 128) >> 8, p1 = (q1 + 128) >> 8;
                    int r0 = q0 - (p0 << 8), r1 = q1 - (p1 << 8);
                    unsigned short hi2 = (unsigned short)((p0 & 0xFF) | ((p1 & 0xFF) << 8));
                    unsigned short lo2 = (unsigned short)((r0 & 0xFF) | ((r1 & 0xFF) << 8));
                    size_t sa = (size_t)row * 1024 +
                                ((((gc >> 4) ^ (row & 7)) << 4) | (gc & 15));
                    __stcg(reinterpret_cast<unsigned short*>(g_h1 + sa), hi2);
                    __stcg(reinterpret_cast<unsigned short*>(g_h0 + sa), lo2);
                }
            }
        }
        par ^= 1;
        epoch++;
        grid_sync(epoch * NBLK);
    }
}

// ================== launcher ===================================================
extern "C" void kernel_launch(void* const* d_in, const int* in_sizes, int n_in,
                              void* d_out, int out_size)
{
    const float* X    = (const float*)d_in[0];
    const float* W_xr = (const float*)d_in[1];
    const float* W_xu = (const float*)d_in[2];
    const float* W_xh = (const float*)d_in[3];
    const float* W_hr = (const float*)d_in[4];
    const float* W_hu = (const float*)d_in[5];
    const float* W_hh = (const float*)d_in[6];
    const float* b_r  = (const float*)d_in[7];
    const float* b_u  = (const float*)d_in[8];
    const float* b_h  = (const float*)d_in[9];
    const float* W_hq = (const float*)d_in[10];
    const float* b_q  = (const float*)d_in[11];

    float* out     = (float*)d_out;
    float* outputs = out;                        // [T,B,O]
    float* states  = out + (size_t)TB_ * O_;     // [T,B,H]

    void *p_x, *p_ah, *p_al, *p_bh, *p_bl;
    cudaGetSymbolAddress(&p_x, g_x);
    cudaGetSymbolAddress(&p_ah, g_Ah);
    cudaGetSymbolAddress(&p_al, g_Al);
    cudaGetSymbolAddress(&p_bh, g_Bh);
    cudaGetSymbolAddress(&p_bl, g_Bl);

    float* xbuf = (float*)p_x;
    __nv_bfloat16* Ah = (__nv_bfloat16*)p_ah;
    __nv_bfloat16* Al = (__nv_bfloat16*)p_al;
    __nv_bfloat16* Bh = (__nv_bfloat16*)p_bh;
    __nv_bfloat16* Bl = (__nv_bfloat16*)p_bl;

    static int smem_set = 0;
    if (!smem_set) {
        cudaFuncSetAttribute(hmma_gemm3_kernel,
                             cudaFuncAttributeMaxDynamicSharedMemorySize, GEMM_SMEM);
        cudaFuncSetAttribute(gru_int8_kernel,
                             cudaFuncAttributeMaxDynamicSharedMemorySize, RSMEM);
        smem_set = 1;
    }

    // 0
    init_kernel<<<(B_ * H_ + 255) / 256, 256>>>();
    // 1: X -> bf16 hi/lo
    split_convert_A<<<TB_ * (H_ / 4) / 256, 256>>>(X, Ah, Al);
    // 2: all 4 projection weights
    split_convert_B4<<<4 * 4096, 256>>>(W_xr, W_xu, W_xh, W_hq);
    // 3: recurrence weights int8
    quantW3<<<3 * 4096, 256>>>(W_hr, W_hu, W_hh);
    // 4: fused input projections
    {
        ProjOut po;
        po.b[0] = b_r; po.b[1] = b_u; po.b[2] = b_h;
        po.c[0] = xbuf; po.c[1] = xbuf + (size_t)TB_ * H_; po.c[2] = xbuf + 2 * (size_t)TB_ * H_;
        dim3 gg(24, TB_ / 128);
        hmma_gemm3_kernel<<<gg, 256, GEMM_SMEM>>>(Ah, Al, Bh, Bl, po);
    }
    // 5: recurrence (also emits bf16 split of states)
    gru_int8_kernel<<<NBLK, 256, RSMEM>>>(states);
    // 6: output projection
    {
        ProjOut po;
        po.b[0] = b_q; po.b[1] = b_q; po.b[2] = b_q;
        po.c[0] = outputs; po.c[1] = outputs; po.c[2] = outputs;
        dim3 gg(8, TB_ / 128);
        hmma_gemm3_kernel<<<gg, 256, GEMM_SMEM>>>(Ah, Al, Bh + 3 * (size_t)H_ * H_,
                                                  Bl + 3 * (size_t)H_ * H_, po);
    }
}